// round 5
// baseline (speedup 1.0000x reference)
#include <cuda_runtime.h>
#include <math.h>

#define QSCALE 0.07216878364870323f
#define L2_10K 0.41524101186092024f
typedef unsigned long long u64;

__device__ __align__(16) float g_qn[32 * 4096];
__device__ __align__(16) float g_qp[32 * 2048];
__device__ __align__(16) float g_q[32 * 32 * 576];
__device__ __align__(16) float g_num[32 * 32 * 512];
__device__ float g_den[32 * 32];
__device__ __align__(16) float g_oh[32 * 4096];

__device__ __forceinline__ u64 pk(float a) { u64 r; asm("mov.b64 %0,{%1,%1};" : "=l"(r) : "f"(a)); return r; }
__device__ __forceinline__ void f2(u64& d, u64 a, u64 b) { asm("fma.rn.f32x2 %0,%1,%2,%0;" : "+l"(d) : "l"(a), "l"(b)); }
__device__ __forceinline__ float flo(u64 v) { return __uint_as_float((unsigned)v); }
__device__ __forceinline__ float fhi(u64 v) { return __uint_as_float((unsigned)(v >> 32)); }

__global__ void zall(float* out, const float* kc, const float* kpe,
                     float* cK, float* cV, const int* pos,
                     const int* bidx, const int* boff)
{
    int i = blockIdx.x * blockDim.x + threadIdx.x, s = gridDim.x * blockDim.x;
    for (int j = i; j < 131072; j += s) { g_qn[j] = 0.f; g_oh[j] = 0.f; }
    for (int j = i; j < 65536; j += s) g_qp[j] = 0.f;
    for (int j = i; j < 589824; j += s) g_q[j] = 0.f;
    for (int j = i; j < 524288; j += s) g_num[j] = 0.f;
    for (int j = i; j < 1024; j += s) g_den[j] = 0.f;
    for (int j = i; j < 163840; j += s) out[j] = 0.f;
    if (blockIdx.x < 32) {  // fused cache scatter
        int b = blockIdx.x, t = threadIdx.x;
        long long row = (long long)bidx[b] * 128 + boff[b];
        if (t < 32) {
            float p = (float)pos[b];
            float ang = p * exp2f(-(float)t * L2_10K);
            float cv = cosf(ang), sv = sinf(ang);
            float x1 = kpe[b * 64 + t], x2 = kpe[b * 64 + 32 + t];
            cK[row * 64 + t] = x1 * cv - x2 * sv;
            cK[row * 64 + 32 + t] = x2 * cv + x1 * sv;
        }
        for (int j = t; j < 512; j += 256) cV[row * 512 + j] = kc[b * 512 + j];
    }
}

// C[32,N] += alpha*A[32,K]@B[K,N]; grid=(N/128, ksplit, nbatch)
__global__ void gemm32(const float* __restrict__ A, const float* __restrict__ B,
                       float* __restrict__ C, int K, int lda, int ldb, int ldc,
                       int Abs, int Bbs, int Cbs, float alpha)
{
    __shared__ float As[32][33];
    __shared__ __align__(16) float Bs[32][128];
    int bat = blockIdx.z;
    A += (long long)bat * Abs; B += (long long)bat * Bbs; C += (long long)bat * Cbs;
    int kchunk = K / gridDim.y, kbeg = blockIdx.y * kchunk;
    int n0 = blockIdx.x * 128, t = threadIdx.x;
    int tx = t & 31, ty = t >> 5;
    u64 acc[4][2] = {};
    for (int k0 = kbeg; k0 < kbeg + kchunk; k0 += 32) {
        {
            int m = t >> 3, kk = (t & 7) * 4;
            float4 a4 = *(const float4*)(A + (long long)m * lda + k0 + kk);
            As[kk][m] = a4.x; As[kk + 1][m] = a4.y; As[kk + 2][m] = a4.z; As[kk + 3][m] = a4.w;
        }
#pragma unroll
        for (int i = 0; i < 4; i++) {
            int e = t + i * 256, kk = e >> 5, c4 = (e & 31) * 4;
            *(float4*)(&Bs[kk][c4]) = *(const float4*)(B + (long long)(k0 + kk) * ldb + n0 + c4);
        }
        __syncthreads();
#pragma unroll
        for (int kk = 0; kk < 32; kk++) {
            u64 b0 = *(u64*)(&Bs[kk][tx * 4]), b1 = *(u64*)(&Bs[kk][tx * 4 + 2]);
#pragma unroll
            for (int i = 0; i < 4; i++) {
                u64 a = pk(As[kk][ty * 4 + i]);
                f2(acc[i][0], a, b0); f2(acc[i][1], a, b1);
            }
        }
        __syncthreads();
    }
#pragma unroll
    for (int i = 0; i < 4; i++) {
        float* dst = C + (long long)(ty * 4 + i) * ldc + n0 + tx * 4;
        atomicAdd(dst, alpha * flo(acc[i][0])); atomicAdd(dst + 1, alpha * fhi(acc[i][0]));
        atomicAdd(dst + 2, alpha * flo(acc[i][1])); atomicAdd(dst + 3, alpha * fhi(acc[i][1]));
    }
}

__global__ void rope_q(const int* __restrict__ pos) {
    int b = blockIdx.x, t = threadIdx.x;
    float p = (float)pos[b];
#pragma unroll
    for (int r = 0; r < 4; r++) {
        int id = t + r * 256, h = id >> 5, i = id & 31;
        float ang = p * exp2f(-(float)i * L2_10K);
        float cv = cosf(ang), sv = sinf(ang);
        float x1 = g_qp[b * 2048 + h * 64 + i];
        float x2 = g_qp[b * 2048 + h * 64 + 32 + i];
        g_q[(b * 32 + h) * 576 + 512 + i] = (x1 * cv - x2 * sv) * QSCALE;
        g_q[(b * 32 + h) * 576 + 544 + i] = (x2 * cv + x1 * sv) * QSCALE;
    }
}

#define ATTN_SMEM (28320 * 4)
__global__ void __launch_bounds__(512, 1)
attn_kernel(const float* __restrict__ cK, const float* __restrict__ cV,
            const int* __restrict__ blist, const int* __restrict__ bgrp,
            const float* __restrict__ bias)
{
    extern __shared__ float sm[];
    float* q_s = sm;              // [32][576]
    float* Vc = q_s + 18432;      // [16][512]
    float* Kc = Vc + 8192;        // [16][64]
    float* p_s = Kc + 1024;       // [32][16]
    float* bias_s = p_s + 512;    // [128]
    float* den_s = bias_s + 128;  // [32]

    int n = blockIdx.x, t = threadIdx.x;
    int lane = t & 31, w = t >> 5;          // 16 warps
    int b = bgrp[n];
    long long blk = blist[n];

    {
        const float4* src = (const float4*)(g_q + (long long)b * 18432);
        float4* dst = (float4*)q_s;
#pragma unroll
        for (int i = 0; i < 9; i++) dst[t + i * 512] = src[t + i * 512];
    }
    if (t < 128) bias_s[t] = bias[n * 128 + t];
    if (t < 32) den_s[t] = 0.f;

    int tx = t & 63, ty = t >> 6;           // ty in [0,8)
    u64 avp[4][4] = {};                     // heads ty+8j, l = tx*8..tx*8+7

    const float4* Vg = (const float4*)(cV + blk * 65536);
    const float4* Kg = (const float4*)(cK + blk * 8192);

    for (int c = 0; c < 8; c++) {
        __syncthreads();
#pragma unroll
        for (int i = 0; i < 4; i++) ((float4*)Vc)[t + i * 512] = Vg[c * 2048 + t + i * 512];
        if (t < 256) ((float4*)Kc)[t] = Kg[c * 256 + t];
        __syncthreads();

        int h0 = w * 2;
        const float* qs0 = q_s + h0 * 576;
#pragma unroll
        for (int tt = 0; tt < 4; tt++) {
            int k0 = tt * 4;
            u64 acc[2][4] = {};
#pragma unroll
            for (int s = 0; s < 8; s++) {
                int d = s * 64 + lane * 2;
                u64 qv0 = *(const u64*)(qs0 + d), qv1 = *(const u64*)(qs0 + 576 + d);
                u64 kv[4];
#pragma unroll
                for (int j = 0; j < 4; j++) kv[j] = *(const u64*)(Vc + (k0 + j) * 512 + d);
#pragma unroll
                for (int j = 0; j < 4; j++) { f2(acc[0][j], qv0, kv[j]); f2(acc[1][j], qv1, kv[j]); }
            }
            {
                int d = lane * 2;
                u64 qv0 = *(const u64*)(qs0 + 512 + d), qv1 = *(const u64*)(qs0 + 1088 + d);
                u64 kv[4];
#pragma unroll
                for (int j = 0; j < 4; j++) kv[j] = *(const u64*)(Kc + (k0 + j) * 64 + d);
#pragma unroll
                for (int j = 0; j < 4; j++) { f2(acc[0][j], qv0, kv[j]); f2(acc[1][j], qv1, kv[j]); }
            }
            float red[2][4];
#pragma unroll
            for (int i = 0; i < 2; i++)
#pragma unroll
                for (int j = 0; j < 4; j++) {
                    float v = flo(acc[i][j]) + fhi(acc[i][j]);
                    v += __shfl_xor_sync(~0u, v, 16); v += __shfl_xor_sync(~0u, v, 8);
                    v += __shfl_xor_sync(~0u, v, 4); v += __shfl_xor_sync(~0u, v, 2);
                    v += __shfl_xor_sync(~0u, v, 1);
                    red[i][j] = v;
                }
            if (lane == 0) {
#pragma unroll
                for (int i = 0; i < 2; i++) {
                    float ds = 0.f;
#pragma unroll
                    for (int j = 0; j < 4; j++) {
                        float p = __expf(red[i][j] + bias_s[c * 16 + k0 + j]);
                        p_s[(h0 + i) * 16 + k0 + j] = p;
                        ds += p;
                    }
                    den_s[h0 + i] += ds;
                }
            }
        }
        __syncthreads();
#pragma unroll
        for (int k = 0; k < 16; k++) {
            double2 dA = ((const double2*)Vc)[k * 128 + tx * 2];
            double2 dB = ((const double2*)Vc)[k * 128 + tx * 2 + 1];
            u64 v0 = __double_as_longlong(dA.x), v1 = __double_as_longlong(dA.y);
            u64 v2 = __double_as_longlong(dB.x), v3 = __double_as_longlong(dB.y);
#pragma unroll
            for (int j = 0; j < 4; j++) {
                u64 pp = pk(p_s[(ty + j * 8) * 16 + k]);
                f2(avp[j][0], pp, v0); f2(avp[j][1], pp, v1);
                f2(avp[j][2], pp, v2); f2(avp[j][3], pp, v3);
            }
        }
    }
    __syncthreads();
#pragma unroll
    for (int j = 0; j < 4; j++) {
        float* dst = g_num + (long long)(b * 32 + ty + j * 8) * 512 + tx * 8;
#pragma unroll
        for (int i = 0; i < 4; i++) {
            atomicAdd(dst + i * 2, flo(avp[j][i]));
            atomicAdd(dst + i * 2 + 1, fhi(avp[j][i]));
        }
    }
    if (t < 32) atomicAdd(&g_den[b * 32 + t], den_s[t]);
}

__global__ void norm_kernel() {
    int i = blockIdx.x * blockDim.x + threadIdx.x;
    g_num[i] = g_num[i] / g_den[i >> 9];
}

extern "C" void kernel_launch(void* const* d_in, const int* in_sizes, int n_in,
                              void* d_out, int out_size)
{
    const float* hid  = (const float*)d_in[0];
    const float* kcn  = (const float*)d_in[1];
    const float* kpe  = (const float*)d_in[2];
    float* cacheK     = (float*)d_in[3];
    float* cacheV     = (float*)d_in[4];
    const float* W_Q  = (const float*)d_in[5];
    const float* W_UK = (const float*)d_in[6];
    const float* W_QR = (const float*)d_in[7];
    const float* W_UV = (const float*)d_in[8];
    const float* W_O  = (const float*)d_in[9];
    const int* pos    = (const int*)d_in[10];
    const int* blist  = (const int*)d_in[11];
    const int* bgrp   = (const int*)d_in[12];
    int o = (in_sizes[13] == 131072) ? 0 : 1;
    const float* bias = (const float*)d_in[13 + o];
    const int* bidx   = (const int*)d_in[14 + o];
    const int* boff   = (const int*)d_in[15 + o];
    float* out = (float*)d_out;

    float *qn, *qp, *q, *num, *oh;
    cudaGetSymbolAddress((void**)&qn, g_qn);
    cudaGetSymbolAddress((void**)&qp, g_qp);
    cudaGetSymbolAddress((void**)&q, g_q);
    cudaGetSymbolAddress((void**)&num, g_num);
    cudaGetSymbolAddress((void**)&oh, g_oh);
    cudaFuncSetAttribute(attn_kernel, cudaFuncAttributeMaxDynamicSharedMemorySize, ATTN_SMEM);

    zall<<<1024, 256>>>(out, kcn, kpe, cacheK, cacheV, pos, bidx, boff);
    gemm32<<<dim3(32, 4, 1), 256>>>(hid, W_Q, qn, 1536, 1536, 4096, 4096, 0, 0, 0, 1.f);
    gemm32<<<dim3(16, 4, 1), 256>>>(hid, W_QR, qp, 1536, 1536, 2048, 2048, 0, 0, 0, 1.f);
    rope_q<<<32, 256>>>(pos);
    gemm32<<<dim3(4, 1, 32), 256>>>(qn, W_UK, q, 128, 4096, 512, 18432, 128, 65536, 576, QSCALE);
    attn_kernel<<<1024, 512, ATTN_SMEM>>>(cacheK, cacheV, blist, bgrp, bias);
    norm_kernel<<<2048, 256>>>();
    gemm32<<<dim3(1, 4, 32), 256>>>(num, W_UV, oh, 512, 16384, 128, 4096, 512, 65536, 128, 1.f);
    gemm32<<<dim3(40, 8, 1), 256>>>(oh, W_O, out, 4096, 4096, 5120, 5120, 0, 0, 0, 1.f);
}

// round 6
// speedup vs baseline: 1.0694x; 1.0694x over previous
#include <cuda_runtime.h>
#include <math.h>

#define QSCALE 0.07216878364870323f
#define L2_10K 0.41524101186092024f
typedef unsigned long long u64;

__device__ __align__(16) float g_qn[32 * 4096];
__device__ __align__(16) float g_qp[32 * 2048];
__device__ __align__(16) float g_q[32 * 32 * 576];
__device__ __align__(16) float g_num[32 * 32 * 512];
__device__ float g_den[32 * 32];
__device__ __align__(16) float g_oh[32 * 4096];

__device__ __forceinline__ u64 pk(float a) { u64 r; asm("mov.b64 %0,{%1,%1};" : "=l"(r) : "f"(a)); return r; }
__device__ __forceinline__ void f2(u64& d, u64 a, u64 b) { asm("fma.rn.f32x2 %0,%1,%2,%0;" : "+l"(d) : "l"(a), "l"(b)); }
__device__ __forceinline__ float flo(u64 v) { return __uint_as_float((unsigned)v); }
__device__ __forceinline__ float fhi(u64 v) { return __uint_as_float((unsigned)(v >> 32)); }

__global__ void zall(float* out, const float* kc, const float* kpe,
                     float* cK, float* cV, const int* pos,
                     const int* bidx, const int* boff)
{
    int i = blockIdx.x * blockDim.x + threadIdx.x, s = gridDim.x * blockDim.x;
    for (int j = i; j < 131072; j += s) { g_qn[j] = 0.f; g_oh[j] = 0.f; }
    for (int j = i; j < 65536; j += s) g_qp[j] = 0.f;
    for (int j = i; j < 589824; j += s) g_q[j] = 0.f;
    for (int j = i; j < 524288; j += s) g_num[j] = 0.f;
    for (int j = i; j < 1024; j += s) g_den[j] = 0.f;
    for (int j = i; j < 163840; j += s) out[j] = 0.f;
    if (blockIdx.x < 32) {
        int b = blockIdx.x, t = threadIdx.x;
        long long row = (long long)bidx[b] * 128 + boff[b];
        if (t < 32) {
            float p = (float)pos[b];
            float ang = p * exp2f(-(float)t * L2_10K);
            float cv = cosf(ang), sv = sinf(ang);
            float x1 = kpe[b * 64 + t], x2 = kpe[b * 64 + 32 + t];
            cK[row * 64 + t] = x1 * cv - x2 * sv;
            cK[row * 64 + 32 + t] = x2 * cv + x1 * sv;
        }
        for (int j = t; j < 512; j += 256) cV[row * 512 + j] = kc[b * 512 + j];
    }
}

// C[32,N] += alpha*A[32,K]@B[K,N]; grid=(N/128, ksplit, nbatch)
__global__ void gemm32(const float* __restrict__ A, const float* __restrict__ B,
                       float* __restrict__ C, int K, int lda, int ldb, int ldc,
                       int Abs, int Bbs, int Cbs, float alpha)
{
    __shared__ float As[32][33];
    __shared__ __align__(16) float Bs[32][128];
    int bat = blockIdx.z;
    A += (long long)bat * Abs; B += (long long)bat * Bbs; C += (long long)bat * Cbs;
    int kchunk = K / gridDim.y, kbeg = blockIdx.y * kchunk;
    int n0 = blockIdx.x * 128, t = threadIdx.x;
    int tx = t & 31, ty = t >> 5;
    u64 acc[4][2] = {};
    for (int k0 = kbeg; k0 < kbeg + kchunk; k0 += 32) {
        {
            int m = t >> 3, kk = (t & 7) * 4;
            float4 a4 = *(const float4*)(A + (long long)m * lda + k0 + kk);
            As[kk][m] = a4.x; As[kk + 1][m] = a4.y; As[kk + 2][m] = a4.z; As[kk + 3][m] = a4.w;
        }
#pragma unroll
        for (int i = 0; i < 4; i++) {
            int e = t + i * 256, kk = e >> 5, c4 = (e & 31) * 4;
            *(float4*)(&Bs[kk][c4]) = *(const float4*)(B + (long long)(k0 + kk) * ldb + n0 + c4);
        }
        __syncthreads();
#pragma unroll
        for (int kk = 0; kk < 32; kk++) {
            u64 b0 = *(u64*)(&Bs[kk][tx * 4]), b1 = *(u64*)(&Bs[kk][tx * 4 + 2]);
#pragma unroll
            for (int i = 0; i < 4; i++) {
                u64 a = pk(As[kk][ty * 4 + i]);
                f2(acc[i][0], a, b0); f2(acc[i][1], a, b1);
            }
        }
        __syncthreads();
    }
#pragma unroll
    for (int i = 0; i < 4; i++) {
        float* dst = C + (long long)(ty * 4 + i) * ldc + n0 + tx * 4;
        atomicAdd(dst, alpha * flo(acc[i][0])); atomicAdd(dst + 1, alpha * fhi(acc[i][0]));
        atomicAdd(dst + 2, alpha * flo(acc[i][1])); atomicAdd(dst + 3, alpha * fhi(acc[i][1]));
    }
}

__global__ void rope_q(const int* __restrict__ pos) {
    int b = blockIdx.x, t = threadIdx.x;
    float p = (float)pos[b];
#pragma unroll
    for (int r = 0; r < 4; r++) {
        int id = t + r * 256, h = id >> 5, i = id & 31;
        float ang = p * exp2f(-(float)i * L2_10K);
        float cv = cosf(ang), sv = sinf(ang);
        float x1 = g_qp[b * 2048 + h * 64 + i];
        float x2 = g_qp[b * 2048 + h * 64 + 32 + i];
        g_q[(b * 32 + h) * 576 + 512 + i] = (x1 * cv - x2 * sv) * QSCALE;
        g_q[(b * 32 + h) * 576 + 544 + i] = (x2 * cv + x1 * sv) * QSCALE;
    }
}

// one CTA = 16 heads of one KV block; grid = 2048
#define ATTN_SMEM (18832 * 4)
__global__ void __launch_bounds__(256, 2)
attn_kernel(const float* __restrict__ cK, const float* __restrict__ cV,
            const int* __restrict__ blist, const int* __restrict__ bgrp,
            const float* __restrict__ bias)
{
    extern __shared__ float sm[];
    float* q_s = sm;              // [16][576]
    float* Vc = q_s + 9216;       // [16][512]
    float* Kc = Vc + 8192;        // [16][64]
    float* p_s = Kc + 1024;       // [16][16]
    float* bias_s = p_s + 256;    // [128]
    float* den_s = bias_s + 128;  // [16]

    int nb = blockIdx.x, n = nb >> 1, hh = nb & 1;
    int t = threadIdx.x, lane = t & 31, w = t >> 5;
    int b = bgrp[n];
    long long blk = blist[n];

    {
        const float4* src = (const float4*)(g_q + (long long)b * 18432 + hh * 9216);
        float4* dst = (float4*)q_s;
#pragma unroll
        for (int i = 0; i < 9; i++) dst[t + i * 256] = src[t + i * 256];
    }
    if (t < 128) bias_s[t] = bias[n * 128 + t];
    if (t < 16) den_s[t] = 0.f;

    int tx = t & 63, ty = t >> 6;     // tx: l-octet, ty: head mod 4
    u64 avp[4][4] = {};               // head ty+4j, l = tx*8..tx*8+7

    const float4* Vg = (const float4*)(cV + blk * 65536);
    const float4* Kg = (const float4*)(cK + blk * 8192);

    for (int c = 0; c < 8; c++) {
        __syncthreads();
#pragma unroll
        for (int i = 0; i < 8; i++) ((float4*)Vc)[t + i * 256] = Vg[c * 2048 + t + i * 256];
        ((float4*)Kc)[t] = Kg[c * 256 + t];
        __syncthreads();

        int h0 = w * 2;                          // local heads h0, h0+1
        const float* qs0 = q_s + h0 * 576;
#pragma unroll
        for (int tt = 0; tt < 4; tt++) {
            int k0 = tt * 4;
            u64 acc[2][4] = {};
#pragma unroll
            for (int s = 0; s < 8; s++) {
                int d = s * 64 + lane * 2;
                u64 qv0 = *(const u64*)(qs0 + d), qv1 = *(const u64*)(qs0 + 576 + d);
                u64 kv[4];
#pragma unroll
                for (int j = 0; j < 4; j++) kv[j] = *(const u64*)(Vc + (k0 + j) * 512 + d);
#pragma unroll
                for (int j = 0; j < 4; j++) { f2(acc[0][j], qv0, kv[j]); f2(acc[1][j], qv1, kv[j]); }
            }
            {
                int d = lane * 2;
                u64 qv0 = *(const u64*)(qs0 + 512 + d), qv1 = *(const u64*)(qs0 + 1088 + d);
                u64 kv[4];
#pragma unroll
                for (int j = 0; j < 4; j++) kv[j] = *(const u64*)(Kc + (k0 + j) * 64 + d);
#pragma unroll
                for (int j = 0; j < 4; j++) { f2(acc[0][j], qv0, kv[j]); f2(acc[1][j], qv1, kv[j]); }
            }
            float red[2][4];
#pragma unroll
            for (int i = 0; i < 2; i++)
#pragma unroll
                for (int j = 0; j < 4; j++) {
                    float v = flo(acc[i][j]) + fhi(acc[i][j]);
                    v += __shfl_xor_sync(~0u, v, 16); v += __shfl_xor_sync(~0u, v, 8);
                    v += __shfl_xor_sync(~0u, v, 4); v += __shfl_xor_sync(~0u, v, 2);
                    v += __shfl_xor_sync(~0u, v, 1);
                    red[i][j] = v;
                }
            if (lane == 0) {
#pragma unroll
                for (int i = 0; i < 2; i++) {
                    float ds = 0.f;
#pragma unroll
                    for (int j = 0; j < 4; j++) {
                        float p = __expf(red[i][j] + bias_s[c * 16 + k0 + j]);
                        p_s[(h0 + i) * 16 + k0 + j] = p;
                        ds += p;
                    }
                    den_s[h0 + i] += ds;
                }
            }
        }
        __syncthreads();
#pragma unroll
        for (int k = 0; k < 16; k++) {
            u64 v0 = ((const u64*)Vc)[k * 256 + tx * 4];
            u64 v1 = ((const u64*)Vc)[k * 256 + tx * 4 + 1];
            u64 v2 = ((const u64*)Vc)[k * 256 + tx * 4 + 2];
            u64 v3 = ((const u64*)Vc)[k * 256 + tx * 4 + 3];
#pragma unroll
            for (int j = 0; j < 4; j++) {
                u64 pp = pk(p_s[(ty + j * 4) * 16 + k]);
                f2(avp[j][0], pp, v0); f2(avp[j][1], pp, v1);
                f2(avp[j][2], pp, v2); f2(avp[j][3], pp, v3);
            }
        }
    }
    __syncthreads();
#pragma unroll
    for (int j = 0; j < 4; j++) {
        float* dst = g_num + (long long)(b * 32 + hh * 16 + ty + j * 4) * 512 + tx * 8;
#pragma unroll
        for (int i = 0; i < 4; i++) {
            atomicAdd(dst + i * 2, flo(avp[j][i]));
            atomicAdd(dst + i * 2 + 1, fhi(avp[j][i]));
        }
    }
    if (t < 16) atomicAdd(&g_den[b * 32 + hh * 16 + t], den_s[t]);
}

__global__ void norm_kernel() {
    int i = blockIdx.x * blockDim.x + threadIdx.x;
    g_num[i] = g_num[i] / g_den[i >> 9];
}

extern "C" void kernel_launch(void* const* d_in, const int* in_sizes, int n_in,
                              void* d_out, int out_size)
{
    const float* hid  = (const float*)d_in[0];
    const float* kcn  = (const float*)d_in[1];
    const float* kpe  = (const float*)d_in[2];
    float* cacheK     = (float*)d_in[3];
    float* cacheV     = (float*)d_in[4];
    const float* W_Q  = (const float*)d_in[5];
    const float* W_UK = (const float*)d_in[6];
    const float* W_QR = (const float*)d_in[7];
    const float* W_UV = (const float*)d_in[8];
    const float* W_O  = (const float*)d_in[9];
    const int* pos    = (const int*)d_in[10];
    const int* blist  = (const int*)d_in[11];
    const int* bgrp   = (const int*)d_in[12];
    int o = (in_sizes[13] == 131072) ? 0 : 1;
    const float* bias = (const float*)d_in[13 + o];
    const int* bidx   = (const int*)d_in[14 + o];
    const int* boff   = (const int*)d_in[15 + o];
    float* out = (float*)d_out;

    float *qn, *qp, *q, *num, *oh;
    cudaGetSymbolAddress((void**)&qn, g_qn);
    cudaGetSymbolAddress((void**)&qp, g_qp);
    cudaGetSymbolAddress((void**)&q, g_q);
    cudaGetSymbolAddress((void**)&num, g_num);
    cudaGetSymbolAddress((void**)&oh, g_oh);
    cudaFuncSetAttribute(attn_kernel, cudaFuncAttributeMaxDynamicSharedMemorySize, ATTN_SMEM);

    zall<<<1024, 256>>>(out, kcn, kpe, cacheK, cacheV, pos, bidx, boff);
    gemm32<<<dim3(32, 4, 1), 256>>>(hid, W_Q, qn, 1536, 1536, 4096, 4096, 0, 0, 0, 1.f);
    gemm32<<<dim3(16, 4, 1), 256>>>(hid, W_QR, qp, 1536, 1536, 2048, 2048, 0, 0, 0, 1.f);
    rope_q<<<32, 256>>>(pos);
    gemm32<<<dim3(4, 1, 32), 256>>>(qn, W_UK, q, 128, 4096, 512, 18432, 128, 65536, 576, QSCALE);
    attn_kernel<<<2048, 256, ATTN_SMEM>>>(cacheK, cacheV, blist, bgrp, bias);
    norm_kernel<<<2048, 256>>>();
    gemm32<<<dim3(1, 4, 32), 256>>>(num, W_UV, oh, 512, 16384, 128, 4096, 512, 65536, 128, 1.f);
    gemm32<<<dim3(40, 8, 1), 256>>>(oh, W_O, out, 4096, 4096, 5120, 5120, 0, 0, 0, 1.f);
}

// round 8
// speedup vs baseline: 1.5552x; 1.4543x over previous
#include <cuda_runtime.h>
#include <math.h>
#include <stdint.h>

#define QSCALE 0.07216878364870323f
#define L2_10K 0.41524101186092024f
typedef unsigned long long u64;

__device__ __align__(16) float g_qn[32 * 4096];
__device__ __align__(16) float g_qp[32 * 2048];
__device__ __align__(16) float g_q[32 * 32 * 576];
__device__ __align__(16) float g_num[32 * 32 * 512];
__device__ float g_den[32 * 32];
__device__ __align__(16) float g_oh[32 * 4096];

__device__ __forceinline__ u64 pk(float a) { u64 r; asm("mov.b64 %0,{%1,%1};" : "=l"(r) : "f"(a)); return r; }
__device__ __forceinline__ void f2(u64& d, u64 a, u64 b) { asm("fma.rn.f32x2 %0,%1,%2,%0;" : "+l"(d) : "l"(a), "l"(b)); }
__device__ __forceinline__ float flo(u64 v) { return __uint_as_float((unsigned)v); }
__device__ __forceinline__ float fhi(u64 v) { return __uint_as_float((unsigned)(v >> 32)); }
__device__ __forceinline__ uint32_t t32(float x) { uint32_t o; asm("cvt.rn.tf32.f32 %0, %1;" : "=r"(o) : "f"(x)); return o; }
__device__ __forceinline__ void mma8(float* d, const uint32_t* a, const uint32_t* b) {
    asm volatile("mma.sync.aligned.m16n8k8.row.col.f32.tf32.tf32.f32 "
        "{%0,%1,%2,%3}, {%4,%5,%6,%7}, {%8,%9}, {%0,%1,%2,%3};"
        : "+f"(d[0]), "+f"(d[1]), "+f"(d[2]), "+f"(d[3])
        : "r"(a[0]), "r"(a[1]), "r"(a[2]), "r"(a[3]), "r"(b[0]), "r"(b[1]));
}

__global__ void zall(float* out, const float* kc, const float* kpe,
                     float* cK, float* cV, const int* pos,
                     const int* bidx, const int* boff)
{
    int i = blockIdx.x * blockDim.x + threadIdx.x, s = gridDim.x * blockDim.x;
    for (int j = i; j < 131072; j += s) { g_qn[j] = 0.f; g_oh[j] = 0.f; }
    for (int j = i; j < 65536; j += s) g_qp[j] = 0.f;
    for (int j = i; j < 589824; j += s) g_q[j] = 0.f;
    for (int j = i; j < 524288; j += s) g_num[j] = 0.f;
    for (int j = i; j < 1024; j += s) g_den[j] = 0.f;
    for (int j = i; j < 163840; j += s) out[j] = 0.f;
    if (blockIdx.x < 32) {
        int b = blockIdx.x, t = threadIdx.x;
        long long row = (long long)bidx[b] * 128 + boff[b];
        if (t < 32) {
            float p = (float)pos[b];
            float ang = p * exp2f(-(float)t * L2_10K);
            float cv = cosf(ang), sv = sinf(ang);
            float x1 = kpe[b * 64 + t], x2 = kpe[b * 64 + 32 + t];
            cK[row * 64 + t] = x1 * cv - x2 * sv;
            cK[row * 64 + 32 + t] = x2 * cv + x1 * sv;
        }
        for (int j = t; j < 512; j += 256) cV[row * 512 + j] = kc[b * 512 + j];
    }
}

__global__ void gemm32(const float* __restrict__ A, const float* __restrict__ B,
                       float* __restrict__ C, int K, int lda, int ldb, int ldc,
                       int Abs, int Bbs, int Cbs, float alpha)
{
    __shared__ float As[32][33];
    __shared__ __align__(16) float Bs[32][128];
    int bat = blockIdx.z;
    A += (long long)bat * Abs; B += (long long)bat * Bbs; C += (long long)bat * Cbs;
    int kchunk = K / gridDim.y, kbeg = blockIdx.y * kchunk;
    int n0 = blockIdx.x * 128, t = threadIdx.x;
    int tx = t & 31, ty = t >> 5;
    u64 acc[4][2] = {};
    for (int k0 = kbeg; k0 < kbeg + kchunk; k0 += 32) {
        {
            int m = t >> 3, kk = (t & 7) * 4;
            float4 a4 = *(const float4*)(A + (long long)m * lda + k0 + kk);
            As[kk][m] = a4.x; As[kk + 1][m] = a4.y; As[kk + 2][m] = a4.z; As[kk + 3][m] = a4.w;
        }
#pragma unroll
        for (int i = 0; i < 4; i++) {
            int e = t + i * 256, kk = e >> 5, c4 = (e & 31) * 4;
            *(float4*)(&Bs[kk][c4]) = *(const float4*)(B + (long long)(k0 + kk) * ldb + n0 + c4);
        }
        __syncthreads();
#pragma unroll
        for (int kk = 0; kk < 32; kk++) {
            u64 b0 = *(u64*)(&Bs[kk][tx * 4]), b1 = *(u64*)(&Bs[kk][tx * 4 + 2]);
#pragma unroll
            for (int i = 0; i < 4; i++) {
                u64 a = pk(As[kk][ty * 4 + i]);
                f2(acc[i][0], a, b0); f2(acc[i][1], a, b1);
            }
        }
        __syncthreads();
    }
#pragma unroll
    for (int i = 0; i < 4; i++) {
        float* dst = C + (long long)(ty * 4 + i) * ldc + n0 + tx * 4;
        atomicAdd(dst, alpha * flo(acc[i][0])); atomicAdd(dst + 1, alpha * fhi(acc[i][0]));
        atomicAdd(dst + 2, alpha * flo(acc[i][1])); atomicAdd(dst + 3, alpha * fhi(acc[i][1]));
    }
}

__global__ void rope_q(const int* __restrict__ pos) {
    int b = blockIdx.x, t = threadIdx.x;
    float p = (float)pos[b];
#pragma unroll
    for (int r = 0; r < 4; r++) {
        int id = t + r * 256, h = id >> 5, i = id & 31;
        float ang = p * exp2f(-(float)i * L2_10K);
        float cv = cosf(ang), sv = sinf(ang);
        float x1 = g_qp[b * 2048 + h * 64 + i];
        float x2 = g_qp[b * 2048 + h * 64 + 32 + i];
        g_q[(b * 32 + h) * 576 + 512 + i] = (x1 * cv - x2 * sv) * QSCALE;
        g_q[(b * 32 + h) * 576 + 544 + i] = (x2 * cv + x1 * sv) * QSCALE;
    }
}

// smem float offsets
#define F_Q   0        // q tf32 [32][580]
#define F_CH  18560    // kcat chunk tf32 [128][68] / AV V fp32 [16][512]
#define F_P   27264    // P [32][130]
#define F_BI  31424    // bias [128]
#define F_DEN 31552    // den [32]
#define A_SZ  (31584 * 4)

__global__ void __launch_bounds__(256, 1)
attn_mma(const float* __restrict__ cK, const float* __restrict__ cV,
         const int* __restrict__ blist, const int* __restrict__ bgrp,
         const float* __restrict__ bias)
{
    extern __shared__ float sm[];
    float* q_s = sm + F_Q;
    float* ch = sm + F_CH;
    float* p_sm = sm + F_P;
    float* bias_s = sm + F_BI;
    float* den_s = sm + F_DEN;
    int n = blockIdx.x, t = threadIdx.x, lane = t & 31, w = t >> 5;
    int b = bgrp[n];
    long long blk = blist[n];
    const float* Vg = cV + blk * 65536;
    const float* Kg = cK + blk * 8192;

    if (t < 128) bias_s[t] = bias[n * 128 + t];
    if (t < 32) den_s[t] = 0.f;
    // stage q -> tf32, stride 580
    {
        const float* gq = g_q + (long long)b * 18432;
        int row = t >> 3;
#pragma unroll
        for (int j = 0; j < 18; j++) {
            int col = (t & 7) * 4 + j * 32;
            float4 v = *(const float4*)(gq + row * 576 + col);
            uint4 o = { t32(v.x), t32(v.y), t32(v.z), t32(v.w) };
            *(uint4*)(q_s + row * 580 + col) = o;
        }
    }

    // ---- phase A: logits via mma.sync, 9 chunks of 64 d ----
    float acc[4][4] = {};   // 4 n-tiles x (c0..c3); warp rows = w*16..w*16+15
    int kr = w * 16 + (lane >> 2), lq = lane & 3;
    for (int c = 0; c < 9; c++) {
        const float* src = (c < 8) ? (Vg + c * 64) : Kg;
        int lds = (c < 8) ? 512 : 64;
        __syncthreads();
#pragma unroll
        for (int i = 0; i < 8; i++) {
            int idx = t + i * 256, row = idx >> 4, col = (idx & 15) * 4;
            float4 v = *(const float4*)(src + row * lds + col);
            uint4 o = { t32(v.x), t32(v.y), t32(v.z), t32(v.w) };
            *(uint4*)(ch + row * 68 + col) = o;
        }
        __syncthreads();
#pragma unroll
        for (int s = 0; s < 8; s++) {
            uint32_t a[4];
            a[0] = __float_as_uint(ch[kr * 68 + s * 8 + lq]);
            a[1] = __float_as_uint(ch[(kr + 8) * 68 + s * 8 + lq]);
            a[2] = __float_as_uint(ch[kr * 68 + s * 8 + lq + 4]);
            a[3] = __float_as_uint(ch[(kr + 8) * 68 + s * 8 + lq + 4]);
#pragma unroll
            for (int nt = 0; nt < 4; nt++) {
                uint32_t bb[2];
                int hb = (nt * 8 + (lane >> 2)) * 580 + c * 64 + s * 8 + lq;
                bb[0] = __float_as_uint(q_s[hb]);
                bb[1] = __float_as_uint(q_s[hb + 4]);
                mma8(acc[nt], a, bb);
            }
        }
    }
    // exp epilogue in registers
    {
        int kr1 = kr + 8;
        float b0 = bias_s[kr], b1 = bias_s[kr1];
#pragma unroll
        for (int nt = 0; nt < 4; nt++) {
            int h0 = nt * 8 + lq * 2, h1 = h0 + 1;
            p_sm[h0 * 130 + kr] = __expf(acc[nt][0] + b0);
            p_sm[h1 * 130 + kr] = __expf(acc[nt][1] + b0);
            p_sm[h0 * 130 + kr1] = __expf(acc[nt][2] + b1);
            p_sm[h1 * 130 + kr1] = __expf(acc[nt][3] + b1);
        }
    }
    __syncthreads();
    {
        int h = t & 31, seg = t >> 5;
        float ds = 0.f;
#pragma unroll
        for (int i = 0; i < 16; i++) ds += p_sm[h * 130 + seg * 16 + i];
        atomicAdd(&den_s[h], ds);
    }

    // ---- phase B: AV on f32x2 cores ----
    int tx = t & 63, ty = t >> 6;
    u64 avp[8][4] = {};
    for (int c = 0; c < 8; c++) {
        __syncthreads();
#pragma unroll
        for (int i = 0; i < 8; i++)
            ((float4*)ch)[t + i * 256] = ((const float4*)Vg)[c * 2048 + t + i * 256];
        __syncthreads();
#pragma unroll
        for (int k = 0; k < 16; k++) {
            u64 v0 = ((const u64*)ch)[k * 256 + tx * 4];
            u64 v1 = ((const u64*)ch)[k * 256 + tx * 4 + 1];
            u64 v2 = ((const u64*)ch)[k * 256 + tx * 4 + 2];
            u64 v3 = ((const u64*)ch)[k * 256 + tx * 4 + 3];
#pragma unroll
            for (int j = 0; j < 8; j++) {
                u64 pp = pk(p_sm[(ty + j * 4) * 130 + c * 16 + k]);
                f2(avp[j][0], pp, v0); f2(avp[j][1], pp, v1);
                f2(avp[j][2], pp, v2); f2(avp[j][3], pp, v3);
            }
        }
    }
    __syncthreads();
#pragma unroll
    for (int j = 0; j < 8; j++) {
        float* dst = g_num + (long long)(b * 32 + ty + j * 4) * 512 + tx * 8;
        atomicAdd(dst + 0, flo(avp[j][0])); atomicAdd(dst + 1, fhi(avp[j][0]));
        atomicAdd(dst + 2, flo(avp[j][1])); atomicAdd(dst + 3, fhi(avp[j][1]));
        atomicAdd(dst + 4, flo(avp[j][2])); atomicAdd(dst + 5, fhi(avp[j][2]));
        atomicAdd(dst + 6, flo(avp[j][3])); atomicAdd(dst + 7, fhi(avp[j][3]));
    }
    if (t < 32) atomicAdd(&g_den[b * 32 + t], den_s[t]);
}

__global__ void norm_kernel() {
    int i = blockIdx.x * blockDim.x + threadIdx.x;
    g_num[i] = g_num[i] / g_den[i >> 9];
}

extern "C" void kernel_launch(void* const* d_in, const int* in_sizes, int n_in,
                              void* d_out, int out_size)
{
    const float* hid  = (const float*)d_in[0];
    const float* kcn  = (const float*)d_in[1];
    const float* kpe  = (const float*)d_in[2];
    float* cacheK     = (float*)d_in[3];
    float* cacheV     = (float*)d_in[4];
    const float* W_Q  = (const float*)d_in[5];
    const float* W_UK = (const float*)d_in[6];
    const float* W_QR = (const float*)d_in[7];
    const float* W_UV = (const float*)d_in[8];
    const float* W_O  = (const float*)d_in[9];
    const int* pos    = (const int*)d_in[10];
    const int* blist  = (const int*)d_in[11];
    const int* bgrp   = (const int*)d_in[12];
    int o = (in_sizes[13] == 131072) ? 0 : 1;
    const float* bias = (const float*)d_in[13 + o];
    const int* bidx   = (const int*)d_in[14 + o];
    const int* boff   = (const int*)d_in[15 + o];
    float* out = (float*)d_out;

    float *qn, *qp, *q, *num, *oh;
    cudaGetSymbolAddress((void**)&qn, g_qn);
    cudaGetSymbolAddress((void**)&qp, g_qp);
    cudaGetSymbolAddress((void**)&q, g_q);
    cudaGetSymbolAddress((void**)&num, g_num);
    cudaGetSymbolAddress((void**)&oh, g_oh);
    cudaFuncSetAttribute(attn_mma, cudaFuncAttributeMaxDynamicSharedMemorySize, A_SZ);

    zall<<<1024, 256>>>(out, kcn, kpe, cacheK, cacheV, pos, bidx, boff);
    gemm32<<<dim3(32, 4, 1), 256>>>(hid, W_Q, qn, 1536, 1536, 4096, 4096, 0, 0, 0, 1.f);
    gemm32<<<dim3(16, 4, 1), 256>>>(hid, W_QR, qp, 1536, 1536, 2048, 2048, 0, 0, 0, 1.f);
    rope_q<<<32, 256>>>(pos);
    gemm32<<<dim3(4, 1, 32), 256>>>(qn, W_UK, q, 128, 4096, 512, 18432, 128, 65536, 576, QSCALE);
    attn_mma<<<1024, 256, A_SZ>>>(cacheK, cacheV, blist, bgrp, bias);
    norm_kernel<<<2048, 256>>>();
    gemm32<<<dim3(1, 4, 32), 256>>>(num, W_UV, oh, 512, 16384, 128, 4096, 512, 65536, 128, 1.f);
    gemm32<<<dim3(40, 8, 1), 256>>>(oh, W_O, out, 4096, 4096, 5120, 5120, 0, 0, 0, 1.f);
}

// round 9
// speedup vs baseline: 2.0646x; 1.3275x over previous
#include <cuda_runtime.h>
#include <math.h>
#include <stdint.h>

#define QSCALE 0.07216878364870323f
#define L2_10K 0.41524101186092024f
typedef unsigned long long u64;

__device__ __align__(16) float g_qn[32 * 4096];
__device__ __align__(16) float g_qp[32 * 2048];
__device__ __align__(16) float g_q[32 * 32 * 576];
__device__ __align__(16) float g_num[32 * 32 * 512];
__device__ float g_den[32 * 32];
__device__ __align__(16) float g_oh[32 * 4096];

__device__ __forceinline__ u64 pk(float a) { u64 r; asm("mov.b64 %0,{%1,%1};" : "=l"(r) : "f"(a)); return r; }
__device__ __forceinline__ void f2(u64& d, u64 a, u64 b) { asm("fma.rn.f32x2 %0,%1,%2,%0;" : "+l"(d) : "l"(a), "l"(b)); }
__device__ __forceinline__ float flo(u64 v) { return __uint_as_float((unsigned)v); }
__device__ __forceinline__ float fhi(u64 v) { return __uint_as_float((unsigned)(v >> 32)); }
__device__ __forceinline__ uint32_t t32(float x) { uint32_t o; asm("cvt.rn.tf32.f32 %0, %1;" : "=r"(o) : "f"(x)); return o; }
__device__ __forceinline__ void mma8(float* d, const uint32_t* a, const uint32_t* b) {
    asm volatile("mma.sync.aligned.m16n8k8.row.col.f32.tf32.tf32.f32 "
        "{%0,%1,%2,%3}, {%4,%5,%6,%7}, {%8,%9}, {%0,%1,%2,%3};"
        : "+f"(d[0]), "+f"(d[1]), "+f"(d[2]), "+f"(d[3])
        : "r"(a[0]), "r"(a[1]), "r"(a[2]), "r"(a[3]), "r"(b[0]), "r"(b[1]));
}

__global__ void zall(float* out, const float* kc, const float* kpe,
                     float* cK, float* cV, const int* pos,
                     const int* bidx, const int* boff)
{
    int i = blockIdx.x * blockDim.x + threadIdx.x, s = gridDim.x * blockDim.x;
    for (int j = i; j < 131072; j += s) { g_qn[j] = 0.f; g_oh[j] = 0.f; }
    for (int j = i; j < 65536; j += s) g_qp[j] = 0.f;
    for (int j = i; j < 589824; j += s) g_q[j] = 0.f;
    for (int j = i; j < 524288; j += s) g_num[j] = 0.f;
    for (int j = i; j < 1024; j += s) g_den[j] = 0.f;
    for (int j = i; j < 163840; j += s) out[j] = 0.f;
    if (blockIdx.x < 32) {
        int b = blockIdx.x, t = threadIdx.x;
        long long row = (long long)bidx[b] * 128 + boff[b];
        if (t < 32) {
            float p = (float)pos[b];
            float ang = p * exp2f(-(float)t * L2_10K);
            float cv = cosf(ang), sv = sinf(ang);
            float x1 = kpe[b * 64 + t], x2 = kpe[b * 64 + 32 + t];
            cK[row * 64 + t] = x1 * cv - x2 * sv;
            cK[row * 64 + 32 + t] = x2 * cv + x1 * sv;
        }
        for (int j = t; j < 512; j += 256) cV[row * 512 + j] = kc[b * 512 + j];
    }
}

__global__ void gemm32(const float* __restrict__ A, const float* __restrict__ B,
                       float* __restrict__ C, int K, int lda, int ldb, int ldc,
                       int Abs, int Bbs, int Cbs, float alpha)
{
    __shared__ float As[32][33];
    __shared__ __align__(16) float Bs[32][128];
    int bat = blockIdx.z;
    A += (long long)bat * Abs; B += (long long)bat * Bbs; C += (long long)bat * Cbs;
    int kchunk = K / gridDim.y, kbeg = blockIdx.y * kchunk;
    int n0 = blockIdx.x * 128, t = threadIdx.x;
    int tx = t & 31, ty = t >> 5;
    u64 acc[4][2] = {};
    for (int k0 = kbeg; k0 < kbeg + kchunk; k0 += 32) {
        {
            int m = t >> 3, kk = (t & 7) * 4;
            float4 a4 = *(const float4*)(A + (long long)m * lda + k0 + kk);
            As[kk][m] = a4.x; As[kk + 1][m] = a4.y; As[kk + 2][m] = a4.z; As[kk + 3][m] = a4.w;
        }
#pragma unroll
        for (int i = 0; i < 4; i++) {
            int e = t + i * 256, kk = e >> 5, c4 = (e & 31) * 4;
            *(float4*)(&Bs[kk][c4]) = *(const float4*)(B + (long long)(k0 + kk) * ldb + n0 + c4);
        }
        __syncthreads();
#pragma unroll
        for (int kk = 0; kk < 32; kk++) {
            u64 b0 = *(u64*)(&Bs[kk][tx * 4]), b1 = *(u64*)(&Bs[kk][tx * 4 + 2]);
#pragma unroll
            for (int i = 0; i < 4; i++) {
                u64 a = pk(As[kk][ty * 4 + i]);
                f2(acc[i][0], a, b0); f2(acc[i][1], a, b1);
            }
        }
        __syncthreads();
    }
#pragma unroll
    for (int i = 0; i < 4; i++) {
        float* dst = C + (long long)(ty * 4 + i) * ldc + n0 + tx * 4;
        atomicAdd(dst, alpha * flo(acc[i][0])); atomicAdd(dst + 1, alpha * fhi(acc[i][0]));
        atomicAdd(dst + 2, alpha * flo(acc[i][1])); atomicAdd(dst + 3, alpha * fhi(acc[i][1]));
    }
}

__global__ void rope_q(const int* __restrict__ pos) {
    int b = blockIdx.x, t = threadIdx.x;
    float p = (float)pos[b];
#pragma unroll
    for (int r = 0; r < 4; r++) {
        int id = t + r * 256, h = id >> 5, i = id & 31;
        float ang = p * exp2f(-(float)i * L2_10K);
        float cv = cosf(ang), sv = sinf(ang);
        float x1 = g_qp[b * 2048 + h * 64 + i];
        float x2 = g_qp[b * 2048 + h * 64 + 32 + i];
        g_q[(b * 32 + h) * 576 + 512 + i] = (x1 * cv - x2 * sv) * QSCALE;
        g_q[(b * 32 + h) * 576 + 544 + i] = (x2 * cv + x1 * sv) * QSCALE;
    }
}

// smem float offsets
#define CHS 584
#define F_Q   0        // q tf32 [32][580]
#define F_CH  18560    // kcat chunk tf32 [32][584] (V cols 0..511, K cols 512..575)
#define F_P   37248    // P tf32 [32h][36] (32 local keys)
#define F_BI  38400    // bias [128]
#define F_DEN 38528    // den [32]
#define A_SZ  (38560 * 4)

__global__ void __launch_bounds__(256, 1)
attn_mma(const float* __restrict__ cK, const float* __restrict__ cV,
         const int* __restrict__ blist, const int* __restrict__ bgrp,
         const float* __restrict__ bias)
{
    extern __shared__ float sm[];
    float* q_s = sm + F_Q;
    float* ch = sm + F_CH;
    float* p_sm = sm + F_P;
    float* bias_s = sm + F_BI;
    float* den_s = sm + F_DEN;
    int n = blockIdx.x, t = threadIdx.x, lane = t & 31, w = t >> 5;
    int b = bgrp[n];
    long long blk = blist[n];
    const float4* Vg = (const float4*)(cV + blk * 65536);
    const float4* Kg = (const float4*)(cK + blk * 8192);

    if (t < 128) bias_s[t] = bias[n * 128 + t];
    if (t < 32) den_s[t] = 0.f;
    // stage q -> tf32, stride 580
    {
        const float* gq = g_q + (long long)b * 18432;
        int row = t >> 3;
#pragma unroll
        for (int j = 0; j < 18; j++) {
            int col = (t & 7) * 4 + j * 32;
            float4 v = *(const float4*)(gq + row * 576 + col);
            uint4 o = { t32(v.x), t32(v.y), t32(v.z), t32(v.w) };
            *(uint4*)(q_s + row * 580 + col) = o;
        }
    }

    int mt = w & 1, nt = w >> 1;          // logits tile: keys mt*16.., heads nt*8..
    int kr = lane >> 2, lq = lane & 3;
    float accav[2][8][4] = {};            // AV accum: m-tile x n-tile x frag

    for (int c = 0; c < 4; c++) {
        __syncthreads();
        // stage 32 keys: V rows + K rows as tf32
#pragma unroll
        for (int i = 0; i < 18; i++) {
            int idx = t + i * 256;
            float4 v; int row, cb;
            if (idx < 4096) { row = idx >> 7; cb = (idx & 127) * 4; v = Vg[(c * 32 + row) * 128 + (idx & 127)]; }
            else { int k2 = idx - 4096; row = k2 >> 4; cb = 512 + (k2 & 15) * 4; v = Kg[(c * 32 + row) * 16 + (k2 & 15)]; }
            uint4 o = { t32(v.x), t32(v.y), t32(v.z), t32(v.w) };
            *(uint4*)(ch + row * CHS + cb) = o;
        }
        __syncthreads();
        // logits: 72 k8-steps
        float acc[4] = {};
        const float* arow0 = ch + (mt * 16 + kr) * CHS;
        const float* brow = q_s + (nt * 8 + kr) * 580;
#pragma unroll
        for (int s = 0; s < 72; s++) {
            uint32_t a[4], bb[2];
            int d0 = s * 8 + lq;
            a[0] = __float_as_uint(arow0[d0]);
            a[1] = __float_as_uint(arow0[8 * CHS + d0]);
            a[2] = __float_as_uint(arow0[d0 + 4]);
            a[3] = __float_as_uint(arow0[8 * CHS + d0 + 4]);
            bb[0] = __float_as_uint(brow[d0]);
            bb[1] = __float_as_uint(brow[d0 + 4]);
            mma8(acc, a, bb);
        }
        // exp + P write (tf32) + den partials
        {
            int key = mt * 16 + kr;
            int h = nt * 8 + lq * 2;
            float b0 = bias_s[c * 32 + key], b1 = bias_s[c * 32 + key + 8];
            float p0 = __expf(acc[0] + b0), p1 = __expf(acc[1] + b0);
            float p2 = __expf(acc[2] + b1), p3 = __expf(acc[3] + b1);
            p_sm[h * 36 + key] = __uint_as_float(t32(p0));
            p_sm[(h + 1) * 36 + key] = __uint_as_float(t32(p1));
            p_sm[h * 36 + key + 8] = __uint_as_float(t32(p2));
            p_sm[(h + 1) * 36 + key + 8] = __uint_as_float(t32(p3));
            float d0 = p0 + p2, d1 = p1 + p3;
            d0 += __shfl_xor_sync(~0u, d0, 4); d1 += __shfl_xor_sync(~0u, d1, 4);
            d0 += __shfl_xor_sync(~0u, d0, 8); d1 += __shfl_xor_sync(~0u, d1, 8);
            d0 += __shfl_xor_sync(~0u, d0, 16); d1 += __shfl_xor_sync(~0u, d1, 16);
            if (lane < 4) {
                atomicAdd(&den_s[nt * 8 + lane * 2], d0);
                atomicAdd(&den_s[nt * 8 + lane * 2 + 1], d1);
            }
        }
        __syncthreads();
        // AV: out[32h x 64l(warp)] += P[32h x 32k] @ V[32k x l]
#pragma unroll
        for (int s = 0; s < 4; s++) {
            uint32_t a0[4], a1[4];
            int k0 = s * 8;
            a0[0] = __float_as_uint(p_sm[kr * 36 + k0 + lq]);
            a0[1] = __float_as_uint(p_sm[(kr + 8) * 36 + k0 + lq]);
            a0[2] = __float_as_uint(p_sm[kr * 36 + k0 + lq + 4]);
            a0[3] = __float_as_uint(p_sm[(kr + 8) * 36 + k0 + lq + 4]);
            a1[0] = __float_as_uint(p_sm[(kr + 16) * 36 + k0 + lq]);
            a1[1] = __float_as_uint(p_sm[(kr + 24) * 36 + k0 + lq]);
            a1[2] = __float_as_uint(p_sm[(kr + 16) * 36 + k0 + lq + 4]);
            a1[3] = __float_as_uint(p_sm[(kr + 24) * 36 + k0 + lq + 4]);
            const float* vb0 = ch + (k0 + lq) * CHS + w * 64 + kr;
            const float* vb1 = ch + (k0 + lq + 4) * CHS + w * 64 + kr;
#pragma unroll
            for (int j = 0; j < 8; j++) {
                uint32_t bb[2];
                bb[0] = __float_as_uint(vb0[j * 8]);
                bb[1] = __float_as_uint(vb1[j * 8]);
                mma8(accav[0][j], a0, bb);
                mma8(accav[1][j], a1, bb);
            }
        }
    }
    __syncthreads();
    // epilogue: atomicAdd into g_num
#pragma unroll
    for (int m = 0; m < 2; m++)
#pragma unroll
        for (int j = 0; j < 8; j++) {
            int h = m * 16 + kr, l = w * 64 + j * 8 + lq * 2;
            float* dst = g_num + (long long)(b * 32 + h) * 512 + l;
            atomicAdd(dst, accav[m][j][0]);
            atomicAdd(dst + 1, accav[m][j][1]);
            atomicAdd(dst + 8 * 512 - l + (l), 0.f);  // no-op keep alignment of code
            float* dst2 = g_num + (long long)(b * 32 + h + 8) * 512 + l;
            atomicAdd(dst2, accav[m][j][2]);
            atomicAdd(dst2 + 1, accav[m][j][3]);
        }
    if (t < 32) atomicAdd(&g_den[b * 32 + t], den_s[t]);
}

__global__ void norm_kernel() {
    int i = blockIdx.x * blockDim.x + threadIdx.x;
    g_num[i] = g_num[i] / g_den[i >> 9];
}

extern "C" void kernel_launch(void* const* d_in, const int* in_sizes, int n_in,
                              void* d_out, int out_size)
{
    const float* hid  = (const float*)d_in[0];
    const float* kcn  = (const float*)d_in[1];
    const float* kpe  = (const float*)d_in[2];
    float* cacheK     = (float*)d_in[3];
    float* cacheV     = (float*)d_in[4];
    const float* W_Q  = (const float*)d_in[5];
    const float* W_UK = (const float*)d_in[6];
    const float* W_QR = (const float*)d_in[7];
    const float* W_UV = (const float*)d_in[8];
    const float* W_O  = (const float*)d_in[9];
    const int* pos    = (const int*)d_in[10];
    const int* blist  = (const int*)d_in[11];
    const int* bgrp   = (const int*)d_in[12];
    int o = (in_sizes[13] == 131072) ? 0 : 1;
    const float* bias = (const float*)d_in[13 + o];
    const int* bidx   = (const int*)d_in[14 + o];
    const int* boff   = (const int*)d_in[15 + o];
    float* out = (float*)d_out;

    float *qn, *qp, *q, *num, *oh;
    cudaGetSymbolAddress((void**)&qn, g_qn);
    cudaGetSymbolAddress((void**)&qp, g_qp);
    cudaGetSymbolAddress((void**)&q, g_q);
    cudaGetSymbolAddress((void**)&num, g_num);
    cudaGetSymbolAddress((void**)&oh, g_oh);
    cudaFuncSetAttribute(attn_mma, cudaFuncAttributeMaxDynamicSharedMemorySize, A_SZ);

    zall<<<1024, 256>>>(out, kcn, kpe, cacheK, cacheV, pos, bidx, boff);
    gemm32<<<dim3(32, 4, 1), 256>>>(hid, W_Q, qn, 1536, 1536, 4096, 4096, 0, 0, 0, 1.f);
    gemm32<<<dim3(16, 4, 1), 256>>>(hid, W_QR, qp, 1536, 1536, 2048, 2048, 0, 0, 0, 1.f);
    rope_q<<<32, 256>>>(pos);
    gemm32<<<dim3(4, 1, 32), 256>>>(qn, W_UK, q, 128, 4096, 512, 18432, 128, 65536, 576, QSCALE);
    attn_mma<<<1024, 256, A_SZ>>>(cacheK, cacheV, blist, bgrp, bias);
    norm_kernel<<<2048, 256>>>();
    gemm32<<<dim3(1, 4, 32), 256>>>(num, W_UV, oh, 512, 16384, 128, 4096, 512, 65536, 128, 1.f);
    gemm32<<<dim3(40, 8, 1), 256>>>(oh, W_O, out, 4096, 4096, 5120, 5120, 0, 0, 0, 1.f);
}

// round 10
// speedup vs baseline: 2.1533x; 1.0429x over previous
#include <cuda_runtime.h>
#include <math.h>
#include <stdint.h>

#define QSCALE 0.07216878364870323f
#define L2_10K 0.41524101186092024f
typedef unsigned long long u64;

__device__ __align__(16) float g_qn[32 * 4096];
__device__ __align__(16) float g_qp[32 * 2048];
__device__ __align__(16) float g_q[32 * 32 * 576];
__device__ __align__(16) float g_num[32 * 32 * 512];
__device__ float g_den[32 * 32];
__device__ __align__(16) float g_oh[32 * 4096];

__device__ __forceinline__ u64 pk(float a) { u64 r; asm("mov.b64 %0,{%1,%1};" : "=l"(r) : "f"(a)); return r; }
__device__ __forceinline__ void f2(u64& d, u64 a, u64 b) { asm("fma.rn.f32x2 %0,%1,%2,%0;" : "+l"(d) : "l"(a), "l"(b)); }
__device__ __forceinline__ float flo(u64 v) { return __uint_as_float((unsigned)v); }
__device__ __forceinline__ float fhi(u64 v) { return __uint_as_float((unsigned)(v >> 32)); }
__device__ __forceinline__ uint32_t t32(float x) { uint32_t o; asm("cvt.rn.tf32.f32 %0, %1;" : "=r"(o) : "f"(x)); return o; }
__device__ __forceinline__ void mma8(float* d, const uint32_t* a, const uint32_t* b) {
    asm volatile("mma.sync.aligned.m16n8k8.row.col.f32.tf32.tf32.f32 "
        "{%0,%1,%2,%3}, {%4,%5,%6,%7}, {%8,%9}, {%0,%1,%2,%3};"
        : "+f"(d[0]), "+f"(d[1]), "+f"(d[2]), "+f"(d[3])
        : "r"(a[0]), "r"(a[1]), "r"(a[2]), "r"(a[3]), "r"(b[0]), "r"(b[1]));
}

__global__ void zall(float* out, const float* kc, const float* kpe,
                     float* cK, float* cV, const int* pos,
                     const int* bidx, const int* boff)
{
    int i = blockIdx.x * blockDim.x + threadIdx.x, s = gridDim.x * blockDim.x;
    for (int j = i; j < 131072; j += s) { g_qn[j] = 0.f; g_oh[j] = 0.f; }
    for (int j = i; j < 65536; j += s) g_qp[j] = 0.f;
    for (int j = i; j < 589824; j += s) g_q[j] = 0.f;
    for (int j = i; j < 524288; j += s) g_num[j] = 0.f;
    for (int j = i; j < 1024; j += s) g_den[j] = 0.f;
    for (int j = i; j < 163840; j += s) out[j] = 0.f;
    if (blockIdx.x < 32) {
        int b = blockIdx.x, t = threadIdx.x;
        long long row = (long long)bidx[b] * 128 + boff[b];
        if (t < 32) {
            float p = (float)pos[b];
            float ang = p * exp2f(-(float)t * L2_10K);
            float cv = cosf(ang), sv = sinf(ang);
            float x1 = kpe[b * 64 + t], x2 = kpe[b * 64 + 32 + t];
            cK[row * 64 + t] = x1 * cv - x2 * sv;
            cK[row * 64 + 32 + t] = x2 * cv + x1 * sv;
        }
        for (int j = t; j < 512; j += 256) cV[row * 512 + j] = kc[b * 512 + j];
    }
}

__global__ void gemm32(const float* __restrict__ A, const float* __restrict__ B,
                       float* __restrict__ C, int K, int lda, int ldb, int ldc,
                       int Abs, int Bbs, int Cbs, float alpha)
{
    __shared__ float As[32][33];
    __shared__ __align__(16) float Bs[32][128];
    int bat = blockIdx.z;
    A += (long long)bat * Abs; B += (long long)bat * Bbs; C += (long long)bat * Cbs;
    int kchunk = K / gridDim.y, kbeg = blockIdx.y * kchunk;
    int n0 = blockIdx.x * 128, t = threadIdx.x;
    int tx = t & 31, ty = t >> 5;
    u64 acc[4][2] = {};
    for (int k0 = kbeg; k0 < kbeg + kchunk; k0 += 32) {
        {
            int m = t >> 3, kk = (t & 7) * 4;
            float4 a4 = *(const float4*)(A + (long long)m * lda + k0 + kk);
            As[kk][m] = a4.x; As[kk + 1][m] = a4.y; As[kk + 2][m] = a4.z; As[kk + 3][m] = a4.w;
        }
#pragma unroll
        for (int i = 0; i < 4; i++) {
            int e = t + i * 256, kk = e >> 5, c4 = (e & 31) * 4;
            *(float4*)(&Bs[kk][c4]) = *(const float4*)(B + (long long)(k0 + kk) * ldb + n0 + c4);
        }
        __syncthreads();
#pragma unroll
        for (int kk = 0; kk < 32; kk++) {
            u64 b0 = *(u64*)(&Bs[kk][tx * 4]), b1 = *(u64*)(&Bs[kk][tx * 4 + 2]);
#pragma unroll
            for (int i = 0; i < 4; i++) {
                u64 a = pk(As[kk][ty * 4 + i]);
                f2(acc[i][0], a, b0); f2(acc[i][1], a, b1);
            }
        }
        __syncthreads();
    }
#pragma unroll
    for (int i = 0; i < 4; i++) {
        float* dst = C + (long long)(ty * 4 + i) * ldc + n0 + tx * 4;
        atomicAdd(dst, alpha * flo(acc[i][0])); atomicAdd(dst + 1, alpha * fhi(acc[i][0]));
        atomicAdd(dst + 2, alpha * flo(acc[i][1])); atomicAdd(dst + 3, alpha * fhi(acc[i][1]));
    }
}

__global__ void rope_q(const int* __restrict__ pos) {
    int b = blockIdx.x, t = threadIdx.x;
    float p = (float)pos[b];
#pragma unroll
    for (int r = 0; r < 4; r++) {
        int id = t + r * 256, h = id >> 5, i = id & 31;
        float ang = p * exp2f(-(float)i * L2_10K);
        float cv = cosf(ang), sv = sinf(ang);
        float x1 = g_qp[b * 2048 + h * 64 + i];
        float x2 = g_qp[b * 2048 + h * 64 + 32 + i];
        g_q[(b * 32 + h) * 576 + 512 + i] = (x1 * cv - x2 * sv) * QSCALE;
        g_q[(b * 32 + h) * 576 + 544 + i] = (x2 * cv + x1 * sv) * QSCALE;
    }
}

// smem float offsets
#define CHS 584
#define F_Q   0        // q tf32 [32][580]
#define F_CH  18560    // kcat chunk tf32 [32][584]
#define F_P   37248    // P tf32 [32h][36]
#define F_BI  38400    // bias [128]
#define F_DEN 38528    // den [32]
#define A_SZ  (38560 * 4)

__global__ void __launch_bounds__(256, 1)
attn_mma(const float* __restrict__ cK, const float* __restrict__ cV,
         const int* __restrict__ blist, const int* __restrict__ bgrp,
         const float* __restrict__ bias)
{
    extern __shared__ float sm[];
    float* q_s = sm + F_Q;
    float* ch = sm + F_CH;
    float* p_sm = sm + F_P;
    float* bias_s = sm + F_BI;
    float* den_s = sm + F_DEN;
    int n = blockIdx.x, t = threadIdx.x, lane = t & 31, w = t >> 5;
    int b = bgrp[n];
    long long blk = blist[n];
    const float4* Vg = (const float4*)(cV + blk * 65536);
    const float4* Kg = (const float4*)(cK + blk * 8192);

    if (t < 128) bias_s[t] = bias[n * 128 + t];
    if (t < 32) den_s[t] = 0.f;
    // stage q -> tf32, stride 580
    {
        const float* gq = g_q + (long long)b * 18432;
        int row = t >> 3;
#pragma unroll
        for (int j = 0; j < 18; j++) {
            int col = (t & 7) * 4 + j * 32;
            float4 v = *(const float4*)(gq + row * 576 + col);
            uint4 o = { t32(v.x), t32(v.y), t32(v.z), t32(v.w) };
            *(uint4*)(q_s + row * 580 + col) = o;
        }
    }

    int mt = w & 1, nt = w >> 1;
    int kr = lane >> 2, lq = lane & 3;
    float accav[2][8][4] = {};
    float4 pre[18];

    // prefetch chunk 0
#pragma unroll
    for (int i = 0; i < 18; i++) {
        int idx = t + i * 256;
        if (idx < 4096) pre[i] = Vg[(idx >> 7) * 128 + (idx & 127)];
        else { int k2 = idx - 4096; pre[i] = Kg[(k2 >> 4) * 16 + (k2 & 15)]; }
    }

    for (int c = 0; c < 4; c++) {
        // store prefetched chunk c (cvt to tf32)
#pragma unroll
        for (int i = 0; i < 18; i++) {
            int idx = t + i * 256;
            int row, cb;
            if (idx < 4096) { row = idx >> 7; cb = (idx & 127) * 4; }
            else { int k2 = idx - 4096; row = k2 >> 4; cb = 512 + (k2 & 15) * 4; }
            uint4 o = { t32(pre[i].x), t32(pre[i].y), t32(pre[i].z), t32(pre[i].w) };
            *(uint4*)(ch + row * CHS + cb) = o;
        }
        __syncthreads();
        // prefetch chunk c+1 (overlaps with logits+AV below)
        if (c < 3) {
#pragma unroll
            for (int i = 0; i < 18; i++) {
                int idx = t + i * 256;
                if (idx < 4096) pre[i] = Vg[((c + 1) * 32 + (idx >> 7)) * 128 + (idx & 127)];
                else { int k2 = idx - 4096; pre[i] = Kg[((c + 1) * 32 + (k2 >> 4)) * 16 + (k2 & 15)]; }
            }
        }
        // logits: 72 k8-steps
        float acc[4] = {};
        const float* arow0 = ch + (mt * 16 + kr) * CHS;
        const float* brow = q_s + (nt * 8 + kr) * 580;
#pragma unroll
        for (int s = 0; s < 72; s++) {
            uint32_t a[4], bb[2];
            int d0 = s * 8 + lq;
            a[0] = __float_as_uint(arow0[d0]);
            a[1] = __float_as_uint(arow0[8 * CHS + d0]);
            a[2] = __float_as_uint(arow0[d0 + 4]);
            a[3] = __float_as_uint(arow0[8 * CHS + d0 + 4]);
            bb[0] = __float_as_uint(brow[d0]);
            bb[1] = __float_as_uint(brow[d0 + 4]);
            mma8(acc, a, bb);
        }
        // exp + P write + den partials
        {
            int key = mt * 16 + kr;
            int h = nt * 8 + lq * 2;
            float b0 = bias_s[c * 32 + key], b1 = bias_s[c * 32 + key + 8];
            float p0 = __expf(acc[0] + b0), p1 = __expf(acc[1] + b0);
            float p2 = __expf(acc[2] + b1), p3 = __expf(acc[3] + b1);
            p_sm[h * 36 + key] = __uint_as_float(t32(p0));
            p_sm[(h + 1) * 36 + key] = __uint_as_float(t32(p1));
            p_sm[h * 36 + key + 8] = __uint_as_float(t32(p2));
            p_sm[(h + 1) * 36 + key + 8] = __uint_as_float(t32(p3));
            float d0 = p0 + p2, d1 = p1 + p3;
            d0 += __shfl_xor_sync(~0u, d0, 4); d1 += __shfl_xor_sync(~0u, d1, 4);
            d0 += __shfl_xor_sync(~0u, d0, 8); d1 += __shfl_xor_sync(~0u, d1, 8);
            d0 += __shfl_xor_sync(~0u, d0, 16); d1 += __shfl_xor_sync(~0u, d1, 16);
            if (lane < 4) {
                atomicAdd(&den_s[nt * 8 + lane * 2], d0);
                atomicAdd(&den_s[nt * 8 + lane * 2 + 1], d1);
            }
        }
        __syncthreads();
        // AV
#pragma unroll
        for (int s = 0; s < 4; s++) {
            uint32_t a0[4], a1[4];
            int k0 = s * 8;
            a0[0] = __float_as_uint(p_sm[kr * 36 + k0 + lq]);
            a0[1] = __float_as_uint(p_sm[(kr + 8) * 36 + k0 + lq]);
            a0[2] = __float_as_uint(p_sm[kr * 36 + k0 + lq + 4]);
            a0[3] = __float_as_uint(p_sm[(kr + 8) * 36 + k0 + lq + 4]);
            a1[0] = __float_as_uint(p_sm[(kr + 16) * 36 + k0 + lq]);
            a1[1] = __float_as_uint(p_sm[(kr + 24) * 36 + k0 + lq]);
            a1[2] = __float_as_uint(p_sm[(kr + 16) * 36 + k0 + lq + 4]);
            a1[3] = __float_as_uint(p_sm[(kr + 24) * 36 + k0 + lq + 4]);
            const float* vb0 = ch + (k0 + lq) * CHS + w * 64 + kr;
            const float* vb1 = ch + (k0 + lq + 4) * CHS + w * 64 + kr;
#pragma unroll
            for (int j = 0; j < 8; j++) {
                uint32_t bb[2];
                bb[0] = __float_as_uint(vb0[j * 8]);
                bb[1] = __float_as_uint(vb1[j * 8]);
                mma8(accav[0][j], a0, bb);
                mma8(accav[1][j], a1, bb);
            }
        }
        __syncthreads();
    }
    // epilogue: atomicAdd into g_num
#pragma unroll
    for (int m = 0; m < 2; m++)
#pragma unroll
        for (int j = 0; j < 8; j++) {
            int h = m * 16 + kr, l = w * 64 + j * 8 + lq * 2;
            float* dst = g_num + (long long)(b * 32 + h) * 512 + l;
            atomicAdd(dst, accav[m][j][0]);
            atomicAdd(dst + 1, accav[m][j][1]);
            float* dst2 = g_num + (long long)(b * 32 + h + 8) * 512 + l;
            atomicAdd(dst2, accav[m][j][2]);
            atomicAdd(dst2 + 1, accav[m][j][3]);
        }
    if (t < 32) atomicAdd(&g_den[b * 32 + t], den_s[t]);
}

__global__ void norm_kernel() {
    int i = blockIdx.x * blockDim.x + threadIdx.x;
    g_num[i] = g_num[i] / g_den[i >> 9];
}

extern "C" void kernel_launch(void* const* d_in, const int* in_sizes, int n_in,
                              void* d_out, int out_size)
{
    const float* hid  = (const float*)d_in[0];
    const float* kcn  = (const float*)d_in[1];
    const float* kpe  = (const float*)d_in[2];
    float* cacheK     = (float*)d_in[3];
    float* cacheV     = (float*)d_in[4];
    const float* W_Q  = (const float*)d_in[5];
    const float* W_UK = (const float*)d_in[6];
    const float* W_QR = (const float*)d_in[7];
    const float* W_UV = (const float*)d_in[8];
    const float* W_O  = (const float*)d_in[9];
    const int* pos    = (const int*)d_in[10];
    const int* blist  = (const int*)d_in[11];
    const int* bgrp   = (const int*)d_in[12];
    int o = (in_sizes[13] == 131072) ? 0 : 1;
    const float* bias = (const float*)d_in[13 + o];
    const int* bidx   = (const int*)d_in[14 + o];
    const int* boff   = (const int*)d_in[15 + o];
    float* out = (float*)d_out;

    float *qn, *qp, *q, *num, *oh;
    cudaGetSymbolAddress((void**)&qn, g_qn);
    cudaGetSymbolAddress((void**)&qp, g_qp);
    cudaGetSymbolAddress((void**)&q, g_q);
    cudaGetSymbolAddress((void**)&num, g_num);
    cudaGetSymbolAddress((void**)&oh, g_oh);
    cudaFuncSetAttribute(attn_mma, cudaFuncAttributeMaxDynamicSharedMemorySize, A_SZ);

    zall<<<1024, 256>>>(out, kcn, kpe, cacheK, cacheV, pos, bidx, boff);
    gemm32<<<dim3(32, 4, 1), 256>>>(hid, W_Q, qn, 1536, 1536, 4096, 4096, 0, 0, 0, 1.f);
    gemm32<<<dim3(16, 4, 1), 256>>>(hid, W_QR, qp, 1536, 1536, 2048, 2048, 0, 0, 0, 1.f);
    rope_q<<<32, 256>>>(pos);
    gemm32<<<dim3(4, 1, 32), 256>>>(qn, W_UK, q, 128, 4096, 512, 18432, 128, 65536, 576, QSCALE);
    attn_mma<<<1024, 256, A_SZ>>>(cacheK, cacheV, blist, bgrp, bias);
    norm_kernel<<<2048, 256>>>();
    gemm32<<<dim3(1, 4, 32), 256>>>(num, W_UV, oh, 512, 16384, 128, 4096, 512, 65536, 128, 1.f);
    gemm32<<<dim3(40, 8, 1), 256>>>(oh, W_O, out, 4096, 4096, 5120, 5120, 0, 0, 0, 1.f);
}

// round 11
// speedup vs baseline: 2.4506x; 1.1381x over previous
#include <cuda_runtime.h>
#include <cuda_fp16.h>
#include <math.h>
#include <stdint.h>

#define QSCALE 0.07216878364870323f
#define L2_10K 0.41524101186092024f
typedef unsigned long long u64;

__device__ __align__(16) float g_qn[32 * 4096];
__device__ __align__(16) float g_qp[32 * 2048];
__device__ __align__(16) float g_q[32 * 32 * 576];
__device__ __align__(16) float g_num[32 * 32 * 512];
__device__ float g_den[32 * 32];
__device__ __align__(16) float g_oh[32 * 4096];

__device__ __forceinline__ u64 pk(float a) { u64 r; asm("mov.b64 %0,{%1,%1};" : "=l"(r) : "f"(a)); return r; }
__device__ __forceinline__ void f2(u64& d, u64 a, u64 b) { asm("fma.rn.f32x2 %0,%1,%2,%0;" : "+l"(d) : "l"(a), "l"(b)); }
__device__ __forceinline__ float flo(u64 v) { return __uint_as_float((unsigned)v); }
__device__ __forceinline__ float fhi(u64 v) { return __uint_as_float((unsigned)(v >> 32)); }
__device__ __forceinline__ uint32_t s2u(const void* p) {
    uint32_t a;
    asm("{ .reg .u64 t; cvta.to.shared.u64 t, %1; cvt.u32.u64 %0, t; }" : "=r"(a) : "l"(p));
    return a;
}
__device__ __forceinline__ void mmah(float* d, const uint32_t* a, const uint32_t* b) {
    asm volatile("mma.sync.aligned.m16n8k16.row.col.f32.f16.f16.f32 "
        "{%0,%1,%2,%3}, {%4,%5,%6,%7}, {%8,%9}, {%0,%1,%2,%3};"
        : "+f"(d[0]), "+f"(d[1]), "+f"(d[2]), "+f"(d[3])
        : "r"(a[0]), "r"(a[1]), "r"(a[2]), "r"(a[3]), "r"(b[0]), "r"(b[1]));
}
__device__ __forceinline__ void ldmx4(uint32_t* r, uint32_t a) {
    asm volatile("ldmatrix.sync.aligned.m8n8.x4.shared.b16 {%0,%1,%2,%3}, [%4];"
        : "=r"(r[0]), "=r"(r[1]), "=r"(r[2]), "=r"(r[3]) : "r"(a));
}
__device__ __forceinline__ void ldmx2(uint32_t* r, uint32_t a) {
    asm volatile("ldmatrix.sync.aligned.m8n8.x2.shared.b16 {%0,%1}, [%2];"
        : "=r"(r[0]), "=r"(r[1]) : "r"(a));
}
__device__ __forceinline__ void ldmx2t(uint32_t* r, uint32_t a) {
    asm volatile("ldmatrix.sync.aligned.m8n8.x2.trans.shared.b16 {%0,%1}, [%2];"
        : "=r"(r[0]), "=r"(r[1]) : "r"(a));
}
__device__ __forceinline__ uint2 h2x2(float4 v) {
    __half2 lo = __floats2half2_rn(v.x, v.y), hi = __floats2half2_rn(v.z, v.w);
    uint2 r;
    r.x = *(uint32_t*)&lo; r.y = *(uint32_t*)&hi;
    return r;
}

__global__ void zall(float* out, const float* kc, const float* kpe,
                     float* cK, float* cV, const int* pos,
                     const int* bidx, const int* boff)
{
    int i = blockIdx.x * blockDim.x + threadIdx.x, s = gridDim.x * blockDim.x;
    for (int j = i; j < 131072; j += s) { g_qn[j] = 0.f; g_oh[j] = 0.f; }
    for (int j = i; j < 65536; j += s) g_qp[j] = 0.f;
    for (int j = i; j < 589824; j += s) g_q[j] = 0.f;
    for (int j = i; j < 524288; j += s) g_num[j] = 0.f;
    for (int j = i; j < 1024; j += s) g_den[j] = 0.f;
    for (int j = i; j < 163840; j += s) out[j] = 0.f;
    if (blockIdx.x < 32) {
        int b = blockIdx.x, t = threadIdx.x;
        long long row = (long long)bidx[b] * 128 + boff[b];
        if (t < 32) {
            float p = (float)pos[b];
            float ang = p * exp2f(-(float)t * L2_10K);
            float cv = cosf(ang), sv = sinf(ang);
            float x1 = kpe[b * 64 + t], x2 = kpe[b * 64 + 32 + t];
            cK[row * 64 + t] = x1 * cv - x2 * sv;
            cK[row * 64 + 32 + t] = x2 * cv + x1 * sv;
        }
        for (int j = t; j < 512; j += 256) cV[row * 512 + j] = kc[b * 512 + j];
    }
}

__global__ void gemm32(const float* __restrict__ A, const float* __restrict__ B,
                       float* __restrict__ C, int K, int lda, int ldb, int ldc,
                       int Abs, int Bbs, int Cbs, float alpha)
{
    __shared__ float As[32][33];
    __shared__ __align__(16) float Bs[32][128];
    int bat = blockIdx.z;
    A += (long long)bat * Abs; B += (long long)bat * Bbs; C += (long long)bat * Cbs;
    int kchunk = K / gridDim.y, kbeg = blockIdx.y * kchunk;
    int n0 = blockIdx.x * 128, t = threadIdx.x;
    int tx = t & 31, ty = t >> 5;
    u64 acc[4][2] = {};
    for (int k0 = kbeg; k0 < kbeg + kchunk; k0 += 32) {
        {
            int m = t >> 3, kk = (t & 7) * 4;
            float4 a4 = *(const float4*)(A + (long long)m * lda + k0 + kk);
            As[kk][m] = a4.x; As[kk + 1][m] = a4.y; As[kk + 2][m] = a4.z; As[kk + 3][m] = a4.w;
        }
#pragma unroll
        for (int i = 0; i < 4; i++) {
            int e = t + i * 256, kk = e >> 5, c4 = (e & 31) * 4;
            *(float4*)(&Bs[kk][c4]) = *(const float4*)(B + (long long)(k0 + kk) * ldb + n0 + c4);
        }
        __syncthreads();
#pragma unroll
        for (int kk = 0; kk < 32; kk++) {
            u64 b0 = *(u64*)(&Bs[kk][tx * 4]), b1 = *(u64*)(&Bs[kk][tx * 4 + 2]);
#pragma unroll
            for (int i = 0; i < 4; i++) {
                u64 a = pk(As[kk][ty * 4 + i]);
                f2(acc[i][0], a, b0); f2(acc[i][1], a, b1);
            }
        }
        __syncthreads();
    }
#pragma unroll
    for (int i = 0; i < 4; i++) {
        float* dst = C + (long long)(ty * 4 + i) * ldc + n0 + tx * 4;
        atomicAdd(dst, alpha * flo(acc[i][0])); atomicAdd(dst + 1, alpha * fhi(acc[i][0]));
        atomicAdd(dst + 2, alpha * flo(acc[i][1])); atomicAdd(dst + 3, alpha * fhi(acc[i][1]));
    }
}

__global__ void rope_q(const int* __restrict__ pos) {
    int b = blockIdx.x, t = threadIdx.x;
    float p = (float)pos[b];
#pragma unroll
    for (int r = 0; r < 4; r++) {
        int id = t + r * 256, h = id >> 5, i = id & 31;
        float ang = p * exp2f(-(float)i * L2_10K);
        float cv = cosf(ang), sv = sinf(ang);
        float x1 = g_qp[b * 2048 + h * 64 + i];
        float x2 = g_qp[b * 2048 + h * 64 + 32 + i];
        g_q[(b * 32 + h) * 576 + 512 + i] = (x1 * cv - x2 * sv) * QSCALE;
        g_q[(b * 32 + h) * 576 + 544 + i] = (x2 * cv + x1 * sv) * QSCALE;
    }
}

// half-based smem layout (byte offsets)
#define CHS 584                 // halves per row
#define H_Q   0                 // q [32][584] half : 37376 B
#define H_CH  37376             // kcat chunk [32][584] half : 37376 B
#define H_P   74752             // P [32][40] half : 2560 B
#define F_BI  77312             // bias [128] f32 : 512 B
#define F_DEN 77824             // den [32] f32 : 128 B
#define A_SZ  77952

__global__ void __launch_bounds__(256, 2)
attn_mma(const float* __restrict__ cK, const float* __restrict__ cV,
         const int* __restrict__ blist, const int* __restrict__ bgrp,
         const float* __restrict__ bias)
{
    extern __shared__ char sm[];
    __half* q_h = (__half*)(sm + H_Q);
    __half* ch_h = (__half*)(sm + H_CH);
    __half* p_h = (__half*)(sm + H_P);
    float* bias_s = (float*)(sm + F_BI);
    float* den_s = (float*)(sm + F_DEN);
    uint32_t sbase = s2u(sm);
    uint32_t qU = sbase + H_Q, chU = sbase + H_CH, pU = sbase + H_P;

    int n = blockIdx.x, t = threadIdx.x, lane = t & 31, w = t >> 5;
    int b = bgrp[n];
    long long blk = blist[n];
    const float4* Vg = (const float4*)(cV + blk * 65536);
    const float4* Kg = (const float4*)(cK + blk * 8192);

    if (t < 128) bias_s[t] = bias[n * 128 + t];
    if (t < 32) den_s[t] = 0.f;
    // stage q -> half
    {
        const float* gq = g_q + (long long)b * 18432;
        int row = t >> 3;
#pragma unroll
        for (int j = 0; j < 18; j++) {
            int col = (t & 7) * 4 + j * 32;
            float4 v = *(const float4*)(gq + row * 576 + col);
            *(uint2*)(ch_h + 0, (void)0, (uint2*)(q_h + row * CHS + col)) = h2x2(v);
        }
    }

    int mt = w & 1, nt = w >> 1;
    int kr = lane >> 2, lq = lane & 3;
    int l15 = lane & 15, l7 = lane & 7;
    float accav[2][8][4] = {};

    // lane-fixed ldmatrix base addresses (bytes)
    uint32_t aAdr = chU + ((mt * 16 + l15) * CHS + (lane >> 4) * 8) * 2;
    uint32_t bAdr = qU + ((nt * 8 + l7) * CHS + ((lane >> 3) & 1) * 8) * 2;
    uint32_t pA0 = pU + (l15 * 40 + (lane >> 4) * 8) * 2;
    uint32_t pA1 = pU + ((16 + l15) * 40 + (lane >> 4) * 8) * 2;
    uint32_t vB = chU + (l15 * CHS + w * 64) * 2;

    for (int c = 0; c < 4; c++) {
        __syncthreads();
        // stage kcat chunk -> half
#pragma unroll
        for (int i = 0; i < 18; i++) {
            int idx = t + i * 256;
            float4 v; int row, cb;
            if (idx < 4096) { row = idx >> 7; cb = (idx & 127) * 4; v = Vg[(c * 32 + row) * 128 + (idx & 127)]; }
            else { int k2 = idx - 4096; row = k2 >> 4; cb = 512 + (k2 & 15) * 4; v = Kg[(c * 32 + row) * 16 + (k2 & 15)]; }
            *(uint2*)(ch_h + row * CHS + cb) = h2x2(v);
        }
        __syncthreads();
        // logits: 36 k16-steps
        float acc[4] = {};
#pragma unroll
        for (int s = 0; s < 36; s++) {
            uint32_t a[4], bb[2];
            ldmx4(a, aAdr + s * 32);
            ldmx2(bb, bAdr + s * 32);
            mmah(acc, a, bb);
        }
        // exp + P(half) write + den partials
        {
            int key = mt * 16 + kr;
            int h = nt * 8 + lq * 2;
            float b0 = bias_s[c * 32 + key], b1 = bias_s[c * 32 + key + 8];
            float p0 = __expf(acc[0] + b0), p1 = __expf(acc[1] + b0);
            float p2 = __expf(acc[2] + b1), p3 = __expf(acc[3] + b1);
            p_h[h * 40 + key] = __float2half_rn(p0);
            p_h[(h + 1) * 40 + key] = __float2half_rn(p1);
            p_h[h * 40 + key + 8] = __float2half_rn(p2);
            p_h[(h + 1) * 40 + key + 8] = __float2half_rn(p3);
            float d0 = p0 + p2, d1 = p1 + p3;
            d0 += __shfl_xor_sync(~0u, d0, 4); d1 += __shfl_xor_sync(~0u, d1, 4);
            d0 += __shfl_xor_sync(~0u, d0, 8); d1 += __shfl_xor_sync(~0u, d1, 8);
            d0 += __shfl_xor_sync(~0u, d0, 16); d1 += __shfl_xor_sync(~0u, d1, 16);
            if (lane < 4) {
                atomicAdd(&den_s[nt * 8 + lane * 2], d0);
                atomicAdd(&den_s[nt * 8 + lane * 2 + 1], d1);
            }
        }
        __syncthreads();
        // AV: D[32h x 64l(warp)] += P[32h x 32k] @ V[32k x l]
#pragma unroll
        for (int s = 0; s < 2; s++) {
            uint32_t a0[4], a1[4];
            ldmx4(a0, pA0 + s * 32);
            ldmx4(a1, pA1 + s * 32);
            uint32_t vBs = vB + s * 16 * CHS * 2;
#pragma unroll
            for (int j = 0; j < 8; j++) {
                uint32_t bb[2];
                ldmx2t(bb, vBs + j * 16);
                mmah(accav[0][j], a0, bb);
                mmah(accav[1][j], a1, bb);
            }
        }
    }
    __syncthreads();
    // epilogue
#pragma unroll
    for (int m = 0; m < 2; m++)
#pragma unroll
        for (int j = 0; j < 8; j++) {
            int h = m * 16 + kr, l = w * 64 + j * 8 + lq * 2;
            float* dst = g_num + (long long)(b * 32 + h) * 512 + l;
            atomicAdd(dst, accav[m][j][0]);
            atomicAdd(dst + 1, accav[m][j][1]);
            float* dst2 = g_num + (long long)(b * 32 + h + 8) * 512 + l;
            atomicAdd(dst2, accav[m][j][2]);
            atomicAdd(dst2 + 1, accav[m][j][3]);
        }
    if (t < 32) atomicAdd(&g_den[b * 32 + t], den_s[t]);
}

__global__ void norm_kernel() {
    int i = blockIdx.x * blockDim.x + threadIdx.x;
    g_num[i] = g_num[i] / g_den[i >> 9];
}

extern "C" void kernel_launch(void* const* d_in, const int* in_sizes, int n_in,
                              void* d_out, int out_size)
{
    const float* hid  = (const float*)d_in[0];
    const float* kcn  = (const float*)d_in[1];
    const float* kpe  = (const float*)d_in[2];
    float* cacheK     = (float*)d_in[3];
    float* cacheV     = (float*)d_in[4];
    const float* W_Q  = (const float*)d_in[5];
    const float* W_UK = (const float*)d_in[6];
    const float* W_QR = (const float*)d_in[7];
    const float* W_UV = (const float*)d_in[8];
    const float* W_O  = (const float*)d_in[9];
    const int* pos    = (const int*)d_in[10];
    const int* blist  = (const int*)d_in[11];
    const int* bgrp   = (const int*)d_in[12];
    int o = (in_sizes[13] == 131072) ? 0 : 1;
    const float* bias = (const float*)d_in[13 + o];
    const int* bidx   = (const int*)d_in[14 + o];
    const int* boff   = (const int*)d_in[15 + o];
    float* out = (float*)d_out;

    float *qn, *qp, *q, *num, *oh;
    cudaGetSymbolAddress((void**)&qn, g_qn);
    cudaGetSymbolAddress((void**)&qp, g_qp);
    cudaGetSymbolAddress((void**)&q, g_q);
    cudaGetSymbolAddress((void**)&num, g_num);
    cudaGetSymbolAddress((void**)&oh, g_oh);
    cudaFuncSetAttribute(attn_mma, cudaFuncAttributeMaxDynamicSharedMemorySize, A_SZ);

    zall<<<1024, 256>>>(out, kcn, kpe, cacheK, cacheV, pos, bidx, boff);
    gemm32<<<dim3(32, 4, 1), 256>>>(hid, W_Q, qn, 1536, 1536, 4096, 4096, 0, 0, 0, 1.f);
    gemm32<<<dim3(16, 4, 1), 256>>>(hid, W_QR, qp, 1536, 1536, 2048, 2048, 0, 0, 0, 1.f);
    rope_q<<<32, 256>>>(pos);
    gemm32<<<dim3(4, 1, 32), 256>>>(qn, W_UK, q, 128, 4096, 512, 18432, 128, 65536, 576, QSCALE);
    attn_mma<<<1024, 256, A_SZ>>>(cacheK, cacheV, blist, bgrp, bias);
    norm_kernel<<<2048, 256>>>();
    gemm32<<<dim3(1, 4, 32), 256>>>(num, W_UV, oh, 512, 16384, 128, 4096, 512, 65536, 128, 1.f);
    gemm32<<<dim3(40, 8, 1), 256>>>(oh, W_O, out, 4096, 4096, 5120, 5120, 0, 0, 0, 1.f);
}

// round 12
// speedup vs baseline: 2.5715x; 1.0493x over previous
#include <cuda_runtime.h>
#include <cuda_fp16.h>
#include <math.h>
#include <stdint.h>

#define QSCALE 0.07216878364870323f
#define L2_10K 0.41524101186092024f
typedef unsigned long long u64;

__device__ __align__(16) float g_qn[32 * 4096];
__device__ __align__(16) float g_qp[32 * 2048];
__device__ __align__(16) float g_q[32 * 32 * 576];
__device__ __align__(16) float g_num[32 * 32 * 512];
__device__ float g_den[32 * 32];
__device__ __align__(16) float g_oh[32 * 4096];

__device__ __forceinline__ u64 pk(float a) { u64 r; asm("mov.b64 %0,{%1,%1};" : "=l"(r) : "f"(a)); return r; }
__device__ __forceinline__ void f2(u64& d, u64 a, u64 b) { asm("fma.rn.f32x2 %0,%1,%2,%0;" : "+l"(d) : "l"(a), "l"(b)); }
__device__ __forceinline__ float flo(u64 v) { return __uint_as_float((unsigned)v); }
__device__ __forceinline__ float fhi(u64 v) { return __uint_as_float((unsigned)(v >> 32)); }
__device__ __forceinline__ uint32_t s2u(const void* p) {
    uint32_t a;
    asm("{ .reg .u64 t; cvta.to.shared.u64 t, %1; cvt.u32.u64 %0, t; }" : "=r"(a) : "l"(p));
    return a;
}
__device__ __forceinline__ void mmah(float* d, const uint32_t* a, const uint32_t* b) {
    asm volatile("mma.sync.aligned.m16n8k16.row.col.f32.f16.f16.f32 "
        "{%0,%1,%2,%3}, {%4,%5,%6,%7}, {%8,%9}, {%0,%1,%2,%3};"
        : "+f"(d[0]), "+f"(d[1]), "+f"(d[2]), "+f"(d[3])
        : "r"(a[0]), "r"(a[1]), "r"(a[2]), "r"(a[3]), "r"(b[0]), "r"(b[1]));
}
__device__ __forceinline__ void ldmx4(uint32_t* r, uint32_t a) {
    asm volatile("ldmatrix.sync.aligned.m8n8.x4.shared.b16 {%0,%1,%2,%3}, [%4];"
        : "=r"(r[0]), "=r"(r[1]), "=r"(r[2]), "=r"(r[3]) : "r"(a));
}
__device__ __forceinline__ void ldmx2(uint32_t* r, uint32_t a) {
    asm volatile("ldmatrix.sync.aligned.m8n8.x2.shared.b16 {%0,%1}, [%2];"
        : "=r"(r[0]), "=r"(r[1]) : "r"(a));
}
__device__ __forceinline__ void ldmx2t(uint32_t* r, uint32_t a) {
    asm volatile("ldmatrix.sync.aligned.m8n8.x2.trans.shared.b16 {%0,%1}, [%2];"
        : "=r"(r[0]), "=r"(r[1]) : "r"(a));
}
__device__ __forceinline__ uint2 h2x2(float4 v) {
    __half2 lo = __floats2half2_rn(v.x, v.y), hi = __floats2half2_rn(v.z, v.w);
    uint2 r;
    r.x = *(uint32_t*)&lo; r.y = *(uint32_t*)&hi;
    return r;
}

__global__ void zall(float* out, const float* kc, const float* kpe,
                     float* cK, float* cV, const int* pos,
                     const int* bidx, const int* boff)
{
    int i = blockIdx.x * blockDim.x + threadIdx.x, s = gridDim.x * blockDim.x;
    for (int j = i; j < 131072; j += s) { g_qn[j] = 0.f; g_oh[j] = 0.f; }
    for (int j = i; j < 65536; j += s) g_qp[j] = 0.f;
    for (int j = i; j < 589824; j += s) g_q[j] = 0.f;
    for (int j = i; j < 524288; j += s) g_num[j] = 0.f;
    for (int j = i; j < 1024; j += s) g_den[j] = 0.f;
    for (int j = i; j < 163840; j += s) out[j] = 0.f;
    if (blockIdx.x < 32) {
        int b = blockIdx.x, t = threadIdx.x;
        long long row = (long long)bidx[b] * 128 + boff[b];
        if (t < 32) {
            float p = (float)pos[b];
            float ang = p * exp2f(-(float)t * L2_10K);
            float cv = cosf(ang), sv = sinf(ang);
            float x1 = kpe[b * 64 + t], x2 = kpe[b * 64 + 32 + t];
            cK[row * 64 + t] = x1 * cv - x2 * sv;
            cK[row * 64 + 32 + t] = x2 * cv + x1 * sv;
        }
        for (int j = t; j < 512; j += 256) cV[row * 512 + j] = kc[b * 512 + j];
    }
}

__global__ void gemm32(const float* __restrict__ A, const float* __restrict__ B,
                       float* __restrict__ C, int K, int lda, int ldb, int ldc,
                       int Abs, int Bbs, int Cbs, float alpha)
{
    __shared__ float As[32][33];
    __shared__ __align__(16) float Bs[32][128];
    int bat = blockIdx.z;
    A += (long long)bat * Abs; B += (long long)bat * Bbs; C += (long long)bat * Cbs;
    int kchunk = K / gridDim.y, kbeg = blockIdx.y * kchunk;
    int n0 = blockIdx.x * 128, t = threadIdx.x;
    int tx = t & 31, ty = t >> 5;
    u64 acc[4][2] = {};
    for (int k0 = kbeg; k0 < kbeg + kchunk; k0 += 32) {
        {
            int m = t >> 3, kk = (t & 7) * 4;
            float4 a4 = *(const float4*)(A + (long long)m * lda + k0 + kk);
            As[kk][m] = a4.x; As[kk + 1][m] = a4.y; As[kk + 2][m] = a4.z; As[kk + 3][m] = a4.w;
        }
#pragma unroll
        for (int i = 0; i < 4; i++) {
            int e = t + i * 256, kk = e >> 5, c4 = (e & 31) * 4;
            *(float4*)(&Bs[kk][c4]) = *(const float4*)(B + (long long)(k0 + kk) * ldb + n0 + c4);
        }
        __syncthreads();
#pragma unroll
        for (int kk = 0; kk < 32; kk++) {
            u64 b0 = *(u64*)(&Bs[kk][tx * 4]), b1 = *(u64*)(&Bs[kk][tx * 4 + 2]);
#pragma unroll
            for (int i = 0; i < 4; i++) {
                u64 a = pk(As[kk][ty * 4 + i]);
                f2(acc[i][0], a, b0); f2(acc[i][1], a, b1);
            }
        }
        __syncthreads();
    }
#pragma unroll
    for (int i = 0; i < 4; i++) {
        float* dst = C + (long long)(ty * 4 + i) * ldc + n0 + tx * 4;
        atomicAdd(dst, alpha * flo(acc[i][0])); atomicAdd(dst + 1, alpha * fhi(acc[i][0]));
        atomicAdd(dst + 2, alpha * flo(acc[i][1])); atomicAdd(dst + 3, alpha * fhi(acc[i][1]));
    }
}

__global__ void rope_q(const int* __restrict__ pos) {
    int b = blockIdx.x, t = threadIdx.x;
    float p = (float)pos[b];
#pragma unroll
    for (int r = 0; r < 4; r++) {
        int id = t + r * 256, h = id >> 5, i = id & 31;
        float ang = p * exp2f(-(float)i * L2_10K);
        float cv = cosf(ang), sv = sinf(ang);
        float x1 = g_qp[b * 2048 + h * 64 + i];
        float x2 = g_qp[b * 2048 + h * 64 + 32 + i];
        g_q[(b * 32 + h) * 576 + 512 + i] = (x1 * cv - x2 * sv) * QSCALE;
        g_q[(b * 32 + h) * 576 + 544 + i] = (x2 * cv + x1 * sv) * QSCALE;
    }
}

// half-based smem layout (byte offsets)
#define CHS 584
#define H_Q   0
#define H_CH  37376
#define H_P   74752
#define F_BI  77312
#define F_DEN 77824
#define A_SZ  77952

// grid = 256: CTA = (seq, part); each CTA does 4 consecutive KV blocks
__global__ void __launch_bounds__(256, 2)
attn_mma(const float* __restrict__ cK, const float* __restrict__ cV,
         const int* __restrict__ blist, const int* __restrict__ bgrp,
         const float* __restrict__ bias)
{
    extern __shared__ char sm[];
    __half* q_h = (__half*)(sm + H_Q);
    __half* ch_h = (__half*)(sm + H_CH);
    __half* p_h = (__half*)(sm + H_P);
    float* bias_s = (float*)(sm + F_BI);
    float* den_s = (float*)(sm + F_DEN);
    uint32_t sbase = s2u(sm);
    uint32_t qU = sbase + H_Q, chU = sbase + H_CH, pU = sbase + H_P;

    int t = threadIdx.x, lane = t & 31, w = t >> 5;
    int seq = blockIdx.x >> 3, part = blockIdx.x & 7;
    int b = bgrp[seq * 32];

    if (t < 32) den_s[t] = 0.f;
    // stage q -> half (once)
    {
        const float* gq = g_q + (long long)b * 18432;
        int row = t >> 3;
#pragma unroll
        for (int j = 0; j < 18; j++) {
            int col = (t & 7) * 4 + j * 32;
            float4 v = *(const float4*)(gq + row * 576 + col);
            *(uint2*)(q_h + row * CHS + col) = h2x2(v);
        }
    }

    int mt = w & 1, nt = w >> 1;
    int kr = lane >> 2, lq = lane & 3;
    int l15 = lane & 15, l7 = lane & 7;
    float accav[2][8][4] = {};

    uint32_t aAdr = chU + ((mt * 16 + l15) * CHS + (lane >> 4) * 8) * 2;
    uint32_t bAdr = qU + ((nt * 8 + l7) * CHS + ((lane >> 3) & 1) * 8) * 2;
    uint32_t pA0 = pU + (l15 * 40 + (lane >> 4) * 8) * 2;
    uint32_t pA1 = pU + ((16 + l15) * 40 + (lane >> 4) * 8) * 2;
    uint32_t vB = chU + (l15 * CHS + w * 64) * 2;

    for (int bi = 0; bi < 4; bi++) {
        int n = seq * 32 + part * 4 + bi;
        long long blk = blist[n];
        const float4* Vg = (const float4*)(cV + blk * 65536);
        const float4* Kg = (const float4*)(cK + blk * 8192);

        for (int c = 0; c < 4; c++) {
            __syncthreads();
            // stage kcat chunk -> half; refresh bias on first chunk of block
#pragma unroll
            for (int i = 0; i < 18; i++) {
                int idx = t + i * 256;
                float4 v; int row, cb;
                if (idx < 4096) { row = idx >> 7; cb = (idx & 127) * 4; v = Vg[(c * 32 + row) * 128 + (idx & 127)]; }
                else { int k2 = idx - 4096; row = k2 >> 4; cb = 512 + (k2 & 15) * 4; v = Kg[(c * 32 + row) * 16 + (k2 & 15)]; }
                *(uint2*)(ch_h + row * CHS + cb) = h2x2(v);
            }
            if (c == 0 && t < 128) bias_s[t] = bias[n * 128 + t];
            __syncthreads();
            // logits: 36 k16-steps
            float acc[4] = {};
#pragma unroll
            for (int s = 0; s < 36; s++) {
                uint32_t a[4], bb[2];
                ldmx4(a, aAdr + s * 32);
                ldmx2(bb, bAdr + s * 32);
                mmah(acc, a, bb);
            }
            // exp + P write + den partials
            {
                int key = mt * 16 + kr;
                int h = nt * 8 + lq * 2;
                float b0 = bias_s[c * 32 + key], b1 = bias_s[c * 32 + key + 8];
                float p0 = __expf(acc[0] + b0), p1 = __expf(acc[1] + b0);
                float p2 = __expf(acc[2] + b1), p3 = __expf(acc[3] + b1);
                p_h[h * 40 + key] = __float2half_rn(p0);
                p_h[(h + 1) * 40 + key] = __float2half_rn(p1);
                p_h[h * 40 + key + 8] = __float2half_rn(p2);
                p_h[(h + 1) * 40 + key + 8] = __float2half_rn(p3);
                float d0 = p0 + p2, d1 = p1 + p3;
                d0 += __shfl_xor_sync(~0u, d0, 4); d1 += __shfl_xor_sync(~0u, d1, 4);
                d0 += __shfl_xor_sync(~0u, d0, 8); d1 += __shfl_xor_sync(~0u, d1, 8);
                d0 += __shfl_xor_sync(~0u, d0, 16); d1 += __shfl_xor_sync(~0u, d1, 16);
                if (lane < 4) {
                    atomicAdd(&den_s[nt * 8 + lane * 2], d0);
                    atomicAdd(&den_s[nt * 8 + lane * 2 + 1], d1);
                }
            }
            __syncthreads();
            // AV
#pragma unroll
            for (int s = 0; s < 2; s++) {
                uint32_t a0[4], a1[4];
                ldmx4(a0, pA0 + s * 32);
                ldmx4(a1, pA1 + s * 32);
                uint32_t vBs = vB + s * 16 * CHS * 2;
#pragma unroll
                for (int j = 0; j < 8; j++) {
                    uint32_t bb[2];
                    ldmx2t(bb, vBs + j * 16);
                    mmah(accav[0][j], a0, bb);
                    mmah(accav[1][j], a1, bb);
                }
            }
        }
    }
    __syncthreads();
    // epilogue (once per CTA)
#pragma unroll
    for (int m = 0; m < 2; m++)
#pragma unroll
        for (int j = 0; j < 8; j++) {
            int h = m * 16 + kr, l = w * 64 + j * 8 + lq * 2;
            float* dst = g_num + (long long)(b * 32 + h) * 512 + l;
            atomicAdd(dst, accav[m][j][0]);
            atomicAdd(dst + 1, accav[m][j][1]);
            float* dst2 = g_num + (long long)(b * 32 + h + 8) * 512 + l;
            atomicAdd(dst2, accav[m][j][2]);
            atomicAdd(dst2 + 1, accav[m][j][3]);
        }
    if (t < 32) atomicAdd(&g_den[b * 32 + t], den_s[t]);
}

__global__ void norm_kernel() {
    int i = blockIdx.x * blockDim.x + threadIdx.x;
    g_num[i] = g_num[i] / g_den[i >> 9];
}

extern "C" void kernel_launch(void* const* d_in, const int* in_sizes, int n_in,
                              void* d_out, int out_size)
{
    const float* hid  = (const float*)d_in[0];
    const float* kcn  = (const float*)d_in[1];
    const float* kpe  = (const float*)d_in[2];
    float* cacheK     = (float*)d_in[3];
    float* cacheV     = (float*)d_in[4];
    const float* W_Q  = (const float*)d_in[5];
    const float* W_UK = (const float*)d_in[6];
    const float* W_QR = (const float*)d_in[7];
    const float* W_UV = (const float*)d_in[8];
    const float* W_O  = (const float*)d_in[9];
    const int* pos    = (const int*)d_in[10];
    const int* blist  = (const int*)d_in[11];
    const int* bgrp   = (const int*)d_in[12];
    int o = (in_sizes[13] == 131072) ? 0 : 1;
    const float* bias = (const float*)d_in[13 + o];
    const int* bidx   = (const int*)d_in[14 + o];
    const int* boff   = (const int*)d_in[15 + o];
    float* out = (float*)d_out;

    float *qn, *qp, *q, *num, *oh;
    cudaGetSymbolAddress((void**)&qn, g_qn);
    cudaGetSymbolAddress((void**)&qp, g_qp);
    cudaGetSymbolAddress((void**)&q, g_q);
    cudaGetSymbolAddress((void**)&num, g_num);
    cudaGetSymbolAddress((void**)&oh, g_oh);
    cudaFuncSetAttribute(attn_mma, cudaFuncAttributeMaxDynamicSharedMemorySize, A_SZ);

    zall<<<1024, 256>>>(out, kcn, kpe, cacheK, cacheV, pos, bidx, boff);
    gemm32<<<dim3(32, 4, 1), 256>>>(hid, W_Q, qn, 1536, 1536, 4096, 4096, 0, 0, 0, 1.f);
    gemm32<<<dim3(16, 4, 1), 256>>>(hid, W_QR, qp, 1536, 1536, 2048, 2048, 0, 0, 0, 1.f);
    rope_q<<<32, 256>>>(pos);
    gemm32<<<dim3(4, 1, 32), 256>>>(qn, W_UK, q, 128, 4096, 512, 18432, 128, 65536, 576, QSCALE);
    attn_mma<<<256, 256, A_SZ>>>(cacheK, cacheV, blist, bgrp, bias);
    norm_kernel<<<2048, 256>>>();
    gemm32<<<dim3(1, 4, 32), 256>>>(num, W_UV, oh, 512, 16384, 128, 4096, 512, 65536, 128, 1.f);
    gemm32<<<dim3(40, 8, 1), 256>>>(oh, W_O, out, 4096, 4096, 5120, 5120, 0, 0, 0, 1.f);
}

// round 13
// speedup vs baseline: 2.7814x; 1.0816x over previous
#include <cuda_runtime.h>
#include <cuda_fp16.h>
#include <math.h>
#include <stdint.h>

#define QSCALE 0.07216878364870323f
#define L2_10K 0.41524101186092024f
typedef unsigned long long u64;

__device__ __align__(16) float g_qn[32 * 4096];
__device__ __align__(16) float g_qp[32 * 2048];
__device__ __align__(16) float g_q[32 * 32 * 576];
__device__ __align__(16) float g_num[32 * 32 * 512];
__device__ float g_den[32 * 32];
__device__ __align__(16) float g_oh[32 * 4096];

__device__ __forceinline__ u64 pk(float a) { u64 r; asm("mov.b64 %0,{%1,%1};" : "=l"(r) : "f"(a)); return r; }
__device__ __forceinline__ void f2(u64& d, u64 a, u64 b) { asm("fma.rn.f32x2 %0,%1,%2,%0;" : "+l"(d) : "l"(a), "l"(b)); }
__device__ __forceinline__ float flo(u64 v) { return __uint_as_float((unsigned)v); }
__device__ __forceinline__ float fhi(u64 v) { return __uint_as_float((unsigned)(v >> 32)); }
__device__ __forceinline__ uint32_t s2u(const void* p) {
    uint32_t a;
    asm("{ .reg .u64 t; cvta.to.shared.u64 t, %1; cvt.u32.u64 %0, t; }" : "=r"(a) : "l"(p));
    return a;
}
__device__ __forceinline__ void mmah(float* d, const uint32_t* a, const uint32_t* b) {
    asm volatile("mma.sync.aligned.m16n8k16.row.col.f32.f16.f16.f32 "
        "{%0,%1,%2,%3}, {%4,%5,%6,%7}, {%8,%9}, {%0,%1,%2,%3};"
        : "+f"(d[0]), "+f"(d[1]), "+f"(d[2]), "+f"(d[3])
        : "r"(a[0]), "r"(a[1]), "r"(a[2]), "r"(a[3]), "r"(b[0]), "r"(b[1]));
}
__device__ __forceinline__ void ldmx4(uint32_t* r, uint32_t a) {
    asm volatile("ldmatrix.sync.aligned.m8n8.x4.shared.b16 {%0,%1,%2,%3}, [%4];"
        : "=r"(r[0]), "=r"(r[1]), "=r"(r[2]), "=r"(r[3]) : "r"(a));
}
__device__ __forceinline__ void ldmx2(uint32_t* r, uint32_t a) {
    asm volatile("ldmatrix.sync.aligned.m8n8.x2.shared.b16 {%0,%1}, [%2];"
        : "=r"(r[0]), "=r"(r[1]) : "r"(a));
}
__device__ __forceinline__ void ldmx2t(uint32_t* r, uint32_t a) {
    asm volatile("ldmatrix.sync.aligned.m8n8.x2.trans.shared.b16 {%0,%1}, [%2];"
        : "=r"(r[0]), "=r"(r[1]) : "r"(a));
}
__device__ __forceinline__ uint2 h2x2(float4 v) {
    __half2 lo = __floats2half2_rn(v.x, v.y), hi = __floats2half2_rn(v.z, v.w);
    uint2 r;
    r.x = *(uint32_t*)&lo; r.y = *(uint32_t*)&hi;
    return r;
}
__device__ __forceinline__ void cpa16(uint32_t dst, const void* src) {
    asm volatile("cp.async.cg.shared.global [%0], [%1], 16;" :: "r"(dst), "l"(src));
}
#define CPA_COMMIT() asm volatile("cp.async.commit_group;" ::: "memory")
#define CPA_WAIT0()  asm volatile("cp.async.wait_group 0;" ::: "memory")

__global__ void zall(float* out, const float* kc, const float* kpe,
                     float* cK, float* cV, const int* pos,
                     const int* bidx, const int* boff)
{
    int i = blockIdx.x * blockDim.x + threadIdx.x, s = gridDim.x * blockDim.x;
    for (int j = i; j < 131072; j += s) { g_qn[j] = 0.f; g_oh[j] = 0.f; }
    for (int j = i; j < 65536; j += s) g_qp[j] = 0.f;
    for (int j = i; j < 589824; j += s) g_q[j] = 0.f;
    for (int j = i; j < 524288; j += s) g_num[j] = 0.f;
    for (int j = i; j < 1024; j += s) g_den[j] = 0.f;
    for (int j = i; j < 163840; j += s) out[j] = 0.f;
    if (blockIdx.x < 32) {
        int b = blockIdx.x, t = threadIdx.x;
        long long row = (long long)bidx[b] * 128 + boff[b];
        if (t < 32) {
            float p = (float)pos[b];
            float ang = p * exp2f(-(float)t * L2_10K);
            float cv = cosf(ang), sv = sinf(ang);
            float x1 = kpe[b * 64 + t], x2 = kpe[b * 64 + 32 + t];
            cK[row * 64 + t] = x1 * cv - x2 * sv;
            cK[row * 64 + 32 + t] = x2 * cv + x1 * sv;
        }
        for (int j = t; j < 512; j += 256) cV[row * 512 + j] = kc[b * 512 + j];
    }
}

__global__ void gemm32(const float* __restrict__ A, const float* __restrict__ B,
                       float* __restrict__ C, int K, int lda, int ldb, int ldc,
                       int Abs, int Bbs, int Cbs, float alpha)
{
    __shared__ float As[32][33];
    __shared__ __align__(16) float Bs[32][128];
    int bat = blockIdx.z;
    A += (long long)bat * Abs; B += (long long)bat * Bbs; C += (long long)bat * Cbs;
    int kchunk = K / gridDim.y, kbeg = blockIdx.y * kchunk;
    int n0 = blockIdx.x * 128, t = threadIdx.x;
    int tx = t & 31, ty = t >> 5;
    u64 acc[4][2] = {};
    for (int k0 = kbeg; k0 < kbeg + kchunk; k0 += 32) {
        {
            int m = t >> 3, kk = (t & 7) * 4;
            float4 a4 = *(const float4*)(A + (long long)m * lda + k0 + kk);
            As[kk][m] = a4.x; As[kk + 1][m] = a4.y; As[kk + 2][m] = a4.z; As[kk + 3][m] = a4.w;
        }
#pragma unroll
        for (int i = 0; i < 4; i++) {
            int e = t + i * 256, kk = e >> 5, c4 = (e & 31) * 4;
            *(float4*)(&Bs[kk][c4]) = *(const float4*)(B + (long long)(k0 + kk) * ldb + n0 + c4);
        }
        __syncthreads();
#pragma unroll
        for (int kk = 0; kk < 32; kk++) {
            u64 b0 = *(u64*)(&Bs[kk][tx * 4]), b1 = *(u64*)(&Bs[kk][tx * 4 + 2]);
#pragma unroll
            for (int i = 0; i < 4; i++) {
                u64 a = pk(As[kk][ty * 4 + i]);
                f2(acc[i][0], a, b0); f2(acc[i][1], a, b1);
            }
        }
        __syncthreads();
    }
#pragma unroll
    for (int i = 0; i < 4; i++) {
        float* dst = C + (long long)(ty * 4 + i) * ldc + n0 + tx * 4;
        atomicAdd(dst, alpha * flo(acc[i][0])); atomicAdd(dst + 1, alpha * fhi(acc[i][0]));
        atomicAdd(dst + 2, alpha * flo(acc[i][1])); atomicAdd(dst + 3, alpha * fhi(acc[i][1]));
    }
}

__global__ void rope_q(const int* __restrict__ pos) {
    int b = blockIdx.x, t = threadIdx.x;
    float p = (float)pos[b];
#pragma unroll
    for (int r = 0; r < 4; r++) {
        int id = t + r * 256, h = id >> 5, i = id & 31;
        float ang = p * exp2f(-(float)i * L2_10K);
        float cv = cosf(ang), sv = sinf(ang);
        float x1 = g_qp[b * 2048 + h * 64 + i];
        float x2 = g_qp[b * 2048 + h * 64 + 32 + i];
        g_q[(b * 32 + h) * 576 + 512 + i] = (x1 * cv - x2 * sv) * QSCALE;
        g_q[(b * 32 + h) * 576 + 544 + i] = (x2 * cv + x1 * sv) * QSCALE;
    }
}

// smem byte offsets
#define CHS 584                 // halves per ch row
#define SST 580                 // floats per stage row
#define H_Q   0                 // q half [32][584] : 37376
#define H_CH  37376             // ch half [32][584] : 37376
#define H_P   74752             // P half [32][40] : 2560
#define F_DEN 77312             // den [32] f32 : 128
#define F_S   77440             // stage fp32 [2][32][580] : 148480
#define A_SZ  225920

// grid = 128: CTA = (seq, part); each CTA does 8 consecutive KV blocks (32 chunks)
__global__ void __launch_bounds__(256, 1)
attn_mma(const float* __restrict__ cK, const float* __restrict__ cV,
         const int* __restrict__ blist, const int* __restrict__ bgrp,
         const float* __restrict__ bias)
{
    extern __shared__ char sm[];
    __half* q_h = (__half*)(sm + H_Q);
    __half* ch_h = (__half*)(sm + H_CH);
    __half* p_h = (__half*)(sm + H_P);
    float* den_s = (float*)(sm + F_DEN);
    uint32_t sbase = s2u(sm);
    uint32_t qU = sbase + H_Q, chU = sbase + H_CH, pU = sbase + H_P, sU = sbase + F_S;

    int t = threadIdx.x, lane = t & 31, w = t >> 5;
    int seq = blockIdx.x >> 2, part = blockIdx.x & 3;
    int nbase = seq * 32 + part * 8;
    int b = bgrp[seq * 32];

    long long blks[8];
#pragma unroll
    for (int i = 0; i < 8; i++) blks[i] = blist[nbase + i];

    if (t < 32) den_s[t] = 0.f;
    // stage q -> half (once)
    {
        const float* gq = g_q + (long long)b * 18432;
        int row = t >> 3;
#pragma unroll
        for (int j = 0; j < 18; j++) {
            int col = (t & 7) * 4 + j * 32;
            float4 v = *(const float4*)(gq + row * 576 + col);
            *(uint2*)(q_h + row * CHS + col) = h2x2(v);
        }
    }

    int mt = w & 1, nt = w >> 1;
    int kr = lane >> 2, lq = lane & 3;
    int l15 = lane & 15, l7 = lane & 7;
    float accav[2][8][4] = {};

    uint32_t aAdr = chU + ((mt * 16 + l15) * CHS + (lane >> 4) * 8) * 2;
    uint32_t bAdr = qU + ((nt * 8 + l7) * CHS + ((lane >> 3) & 1) * 8) * 2;
    uint32_t pA0 = pU + (l15 * 40 + (lane >> 4) * 8) * 2;
    uint32_t pA1 = pU + ((16 + l15) * 40 + (lane >> 4) * 8) * 2;
    uint32_t vB = chU + (l15 * CHS + w * 64) * 2;

    // thread's fixed stage mapping
    int rowV[18], offS[18];        // dest smem byte offsets within a stage buffer
    const float* srcV[18];         // gmem base offsets recomputed per chunk
    // precompute structure of mapping
#pragma unroll
    for (int i = 0; i < 18; i++) {
        int idx = t + i * 256;
        if (idx < 4096) { rowV[i] = idx >> 7; offS[i] = rowV[i] * (SST * 4) + (idx & 127) * 16; }
        else { int k2 = idx - 4096; rowV[i] = k2 >> 4; offS[i] = rowV[i] * (SST * 4) + 2048 + (k2 & 15) * 16; }
    }

    // stage chunk 0 into buffer 0
    {
        const float* Vg = cV + blks[0] * 65536;
        const float* Kg = cK + blks[0] * 8192;
#pragma unroll
        for (int i = 0; i < 18; i++) {
            int idx = t + i * 256;
            const float* src;
            if (idx < 4096) src = Vg + rowV[i] * 512 + (idx & 127) * 4;
            else src = Kg + rowV[i] * 64 + ((idx - 4096) & 15) * 4;
            cpa16(sU + offS[i], src);
        }
        CPA_COMMIT();
    }

    for (int cc = 0; cc < 32; cc++) {
        int sb = cc & 1;
        uint32_t Sb = sU + sb * 148480 / 2;   // 74240 per buffer
        CPA_WAIT0();
        __syncthreads();                      // prev AV done; stage data visible
        // convert own bytes S[sb] -> ch
#pragma unroll
        for (int i = 0; i < 18; i++) {
            int idx = t + i * 256;
            float4 v = *(const float4*)(sm + (Sb - sbase) + offS[i]);
            int colh = (idx < 4096) ? (idx & 127) * 4 : 512 + ((idx - 4096) & 15) * 4;
            *(uint2*)(ch_h + rowV[i] * CHS + colh) = h2x2(v);
        }
        // prefetch next chunk
        if (cc < 31) {
            int nc = cc + 1;
            const float* Vg = cV + blks[nc >> 2] * 65536;
            const float* Kg = cK + blks[nc >> 2] * 8192;
            int c2 = (nc & 3) * 32;
            uint32_t Sn = sU + (1 - sb) * 74240;
#pragma unroll
            for (int i = 0; i < 18; i++) {
                int idx = t + i * 256;
                const float* src;
                if (idx < 4096) src = Vg + (c2 + rowV[i]) * 512 + (idx & 127) * 4;
                else src = Kg + (c2 + rowV[i]) * 64 + ((idx - 4096) & 15) * 4;
                cpa16(Sn + offS[i], src);
            }
            CPA_COMMIT();
        }
        // bias prefetch (consumed after logits)
        int n = nbase + (cc >> 2), c = cc & 3;
        float bb0 = bias[n * 128 + c * 32 + mt * 16 + kr];
        float bb1 = bias[n * 128 + c * 32 + mt * 16 + kr + 8];
        __syncthreads();                      // ch ready
        // logits: 36 k16-steps, 4 independent accumulators
        float la[4][4] = {};
#pragma unroll
        for (int s = 0; s < 36; s++) {
            uint32_t a[4], bb[2];
            ldmx4(a, aAdr + s * 32);
            ldmx2(bb, bAdr + s * 32);
            mmah(la[s & 3], a, bb);
        }
        float acc[4];
#pragma unroll
        for (int i = 0; i < 4; i++) acc[i] = (la[0][i] + la[1][i]) + (la[2][i] + la[3][i]);
        // exp + P write + den partials
        {
            int key = mt * 16 + kr;
            int h = nt * 8 + lq * 2;
            float p0 = __expf(acc[0] + bb0), p1 = __expf(acc[1] + bb0);
            float p2 = __expf(acc[2] + bb1), p3 = __expf(acc[3] + bb1);
            p_h[h * 40 + key] = __float2half_rn(p0);
            p_h[(h + 1) * 40 + key] = __float2half_rn(p1);
            p_h[h * 40 + key + 8] = __float2half_rn(p2);
            p_h[(h + 1) * 40 + key + 8] = __float2half_rn(p3);
            float d0 = p0 + p2, d1 = p1 + p3;
            d0 += __shfl_xor_sync(~0u, d0, 4); d1 += __shfl_xor_sync(~0u, d1, 4);
            d0 += __shfl_xor_sync(~0u, d0, 8); d1 += __shfl_xor_sync(~0u, d1, 8);
            d0 += __shfl_xor_sync(~0u, d0, 16); d1 += __shfl_xor_sync(~0u, d1, 16);
            if (lane < 4) {
                atomicAdd(&den_s[nt * 8 + lane * 2], d0);
                atomicAdd(&den_s[nt * 8 + lane * 2 + 1], d1);
            }
        }
        __syncthreads();                      // P ready
        // AV
#pragma unroll
        for (int s = 0; s < 2; s++) {
            uint32_t a0[4], a1[4];
            ldmx4(a0, pA0 + s * 32);
            ldmx4(a1, pA1 + s * 32);
            uint32_t vBs = vB + s * 16 * CHS * 2;
#pragma unroll
            for (int j = 0; j < 8; j++) {
                uint32_t bb[2];
                ldmx2t(bb, vBs + j * 16);
                mmah(accav[0][j], a0, bb);
                mmah(accav[1][j], a1, bb);
            }
        }
    }
    __syncthreads();
    // epilogue (once per CTA)
#pragma unroll
    for (int m = 0; m < 2; m++)
#pragma unroll
        for (int j = 0; j < 8; j++) {
            int h = m * 16 + kr, l = w * 64 + j * 8 + lq * 2;
            float* dst = g_num + (long long)(b * 32 + h) * 512 + l;
            atomicAdd(dst, accav[m][j][0]);
            atomicAdd(dst + 1, accav[m][j][1]);
            float* dst2 = g_num + (long long)(b * 32 + h + 8) * 512 + l;
            atomicAdd(dst2, accav[m][j][2]);
            atomicAdd(dst2 + 1, accav[m][j][3]);
        }
    if (t < 32) atomicAdd(&g_den[b * 32 + t], den_s[t]);
}

__global__ void norm_kernel() {
    int i = blockIdx.x * blockDim.x + threadIdx.x;
    g_num[i] = g_num[i] / g_den[i >> 9];
}

extern "C" void kernel_launch(void* const* d_in, const int* in_sizes, int n_in,
                              void* d_out, int out_size)
{
    const float* hid  = (const float*)d_in[0];
    const float* kcn  = (const float*)d_in[1];
    const float* kpe  = (const float*)d_in[2];
    float* cacheK     = (float*)d_in[3];
    float* cacheV     = (float*)d_in[4];
    const float* W_Q  = (const float*)d_in[5];
    const float* W_UK = (const float*)d_in[6];
    const float* W_QR = (const float*)d_in[7];
    const float* W_UV = (const float*)d_in[8];
    const float* W_O  = (const float*)d_in[9];
    const int* pos    = (const int*)d_in[10];
    const int* blist  = (const int*)d_in[11];
    const int* bgrp   = (const int*)d_in[12];
    int o = (in_sizes[13] == 131072) ? 0 : 1;
    const float* bias = (const float*)d_in[13 + o];
    const int* bidx   = (const int*)d_in[14 + o];
    const int* boff   = (const int*)d_in[15 + o];
    float* out = (float*)d_out;

    float *qn, *qp, *q, *num, *oh;
    cudaGetSymbolAddress((void**)&qn, g_qn);
    cudaGetSymbolAddress((void**)&qp, g_qp);
    cudaGetSymbolAddress((void**)&q, g_q);
    cudaGetSymbolAddress((void**)&num, g_num);
    cudaGetSymbolAddress((void**)&oh, g_oh);
    cudaFuncSetAttribute(attn_mma, cudaFuncAttributeMaxDynamicSharedMemorySize, A_SZ);

    zall<<<1024, 256>>>(out, kcn, kpe, cacheK, cacheV, pos, bidx, boff);
    gemm32<<<dim3(32, 4, 1), 256>>>(hid, W_Q, qn, 1536, 1536, 4096, 4096, 0, 0, 0, 1.f);
    gemm32<<<dim3(16, 4, 1), 256>>>(hid, W_QR, qp, 1536, 1536, 2048, 2048, 0, 0, 0, 1.f);
    rope_q<<<32, 256>>>(pos);
    gemm32<<<dim3(4, 1, 32), 256>>>(qn, W_UK, q, 128, 4096, 512, 18432, 128, 65536, 576, QSCALE);
    attn_mma<<<128, 256, A_SZ>>>(cacheK, cacheV, blist, bgrp, bias);
    norm_kernel<<<2048, 256>>>();
    gemm32<<<dim3(1, 4, 32), 256>>>(num, W_UV, oh, 512, 16384, 128, 4096, 512, 65536, 128, 1.f);
    gemm32<<<dim3(40, 8, 1), 256>>>(oh, W_O, out, 4096, 4096, 5120, 5120, 0, 0, 0, 1.f);
}